// round 1
// baseline (speedup 1.0000x reference)
#include <cuda_runtime.h>

#define BB 4
#define SS 1024
#define DD 1024
#define HH 16
#define HDIM 64
#define NBH (BB*HH)

// Scratch (allocation-free): split-head activations [B,H,S,HD]
__device__ float g_qh[NBH*SS*HDIM];
__device__ float g_kh[NBH*SS*HDIM];
__device__ float g_vh[NBH*SS*HDIM];
__device__ float g_y [NBH*SS*HDIM];

// ---------------------------------------------------------------------------
// Fused GEMM + bias + ReLU.  C[m][n] = relu(sum_k A[m][k]*W[n][k] + bias[n])
// Both A and W are row-major with K contiguous (torch Linear: x @ W^T).
// IN_SPLIT:  A is read from [B,H,S,HD] split-head layout (m=b*S+s, k=h*64+hd)
// OUT_SPLIT: C is written to [B,H,S,HD] split-head layout (n=h*64+hd)
// ---------------------------------------------------------------------------
#define GBM 128
#define GBN 128
#define GBK 16
#define TST 132   // smem row stride (multiple of 4 for float4, avoids worst conflicts)

template<bool IN_SPLIT, bool OUT_SPLIT>
__global__ void __launch_bounds__(256, 2) gemm_relu(
    const float* __restrict__ A, const float* __restrict__ W,
    const float* __restrict__ bias, float* __restrict__ C,
    int M, int N, int K)
{
    __shared__ float As[GBK*TST];
    __shared__ float Bs[GBK*TST];
    const int tid = threadIdx.x;
    const int tx = tid & 15;
    const int ty = tid >> 4;
    const int bm = blockIdx.y * GBM;
    const int bn = blockIdx.x * GBN;

    float acc[8][8];
    #pragma unroll
    for (int i = 0; i < 8; i++)
        #pragma unroll
        for (int j = 0; j < 8; j++) acc[i][j] = 0.f;

    for (int k0 = 0; k0 < K; k0 += GBK) {
        #pragma unroll
        for (int i = 0; i < 2; i++) {
            int idx = tid + i*256;
            int row = idx >> 2;           // 0..127
            int kq  = (idx & 3) << 2;     // 0,4,8,12
            int gk  = k0 + kq;
            float4 va;
            if (IN_SPLIT) {
                int gm = bm + row;
                const float* p = A + ((size_t)((gm >> 10)*HH + (gk >> 6)))*(SS*HDIM)
                                   + (size_t)(gm & 1023)*HDIM + (gk & 63);
                va = *(const float4*)p;
            } else {
                va = *(const float4*)(A + (size_t)(bm + row)*K + gk);
            }
            As[(kq+0)*TST + row] = va.x;
            As[(kq+1)*TST + row] = va.y;
            As[(kq+2)*TST + row] = va.z;
            As[(kq+3)*TST + row] = va.w;

            float4 vb = *(const float4*)(W + (size_t)(bn + row)*K + gk);
            Bs[(kq+0)*TST + row] = vb.x;
            Bs[(kq+1)*TST + row] = vb.y;
            Bs[(kq+2)*TST + row] = vb.z;
            Bs[(kq+3)*TST + row] = vb.w;
        }
        __syncthreads();

        #pragma unroll
        for (int kk = 0; kk < GBK; kk++) {
            float a[8], b[8];
            float4 t;
            t = *(const float4*)&As[kk*TST + ty*4];      a[0]=t.x; a[1]=t.y; a[2]=t.z; a[3]=t.w;
            t = *(const float4*)&As[kk*TST + ty*4 + 64]; a[4]=t.x; a[5]=t.y; a[6]=t.z; a[7]=t.w;
            t = *(const float4*)&Bs[kk*TST + tx*4];      b[0]=t.x; b[1]=t.y; b[2]=t.z; b[3]=t.w;
            t = *(const float4*)&Bs[kk*TST + tx*4 + 64]; b[4]=t.x; b[5]=t.y; b[6]=t.z; b[7]=t.w;
            #pragma unroll
            for (int i = 0; i < 8; i++)
                #pragma unroll
                for (int j = 0; j < 8; j++)
                    acc[i][j] += a[i]*b[j];
        }
        __syncthreads();
    }

    #pragma unroll
    for (int ih = 0; ih < 2; ih++) {
        #pragma unroll
        for (int ii = 0; ii < 4; ii++) {
            int m = bm + ty*4 + ii + ih*64;
            #pragma unroll
            for (int jh = 0; jh < 2; jh++) {
                int n = bn + tx*4 + jh*64;
                float4 bv = *(const float4*)(bias + n);
                float4 r;
                r.x = fmaxf(acc[ih*4+ii][jh*4+0] + bv.x, 0.f);
                r.y = fmaxf(acc[ih*4+ii][jh*4+1] + bv.y, 0.f);
                r.z = fmaxf(acc[ih*4+ii][jh*4+2] + bv.z, 0.f);
                r.w = fmaxf(acc[ih*4+ii][jh*4+3] + bv.w, 0.f);
                if (OUT_SPLIT) {
                    float* p = C + ((size_t)((m >> 10)*HH + (n >> 6)))*(SS*HDIM)
                                 + (size_t)(m & 1023)*HDIM + (n & 63);
                    *(float4*)p = r;
                } else {
                    *(float4*)(C + (size_t)m*N + n) = r;
                }
            }
        }
    }
}

// ---------------------------------------------------------------------------
// Causal flash attention, fp32. One block per (64-row query tile, b*h).
// 256 threads as 16x16; each thread: 4 query rows x 4 cols.
// Q pre-scaled by 1/sqrt(HD). Masked scores set to exactly -1e9 (matches ref).
// ---------------------------------------------------------------------------
#define FST 68   // smem row stride

__global__ void __launch_bounds__(256) flash_attn(
    const float* __restrict__ Q, const float* __restrict__ K,
    const float* __restrict__ V, float* __restrict__ Y)
{
    extern __shared__ float smf[];
    float* Qs  = smf;                 // [64][FST]  (row = query, col = d)
    float* KsT = Qs  + 64*FST;        // [64][FST]  (row = d, col = key)  TRANSPOSED
    float* Vs  = KsT + 64*FST;        // [64][FST]  (row = key, col = d)
    float* Ps  = Vs  + 64*FST;        // [64][FST]  (row = query, col = key)

    const int tid = threadIdx.x;
    const int tx = tid & 15;
    const int ty = tid >> 4;
    const int qt = blockIdx.x;        // query tile (64 rows)
    const int bh = blockIdx.y;

    const float* Qb = Q + (size_t)bh*SS*HDIM + (size_t)qt*64*HDIM;
    const float* Kb = K + (size_t)bh*SS*HDIM;
    const float* Vb = V + (size_t)bh*SS*HDIM;

    // Load Q tile, folding in the 1/sqrt(64) scale
    #pragma unroll
    for (int i = 0; i < 4; i++) {
        int idx = tid + i*256;
        int row = idx >> 4;
        int c4  = (idx & 15) << 2;
        float4 v = *(const float4*)(Qb + row*HDIM + c4);
        v.x *= 0.125f; v.y *= 0.125f; v.z *= 0.125f; v.w *= 0.125f;
        *(float4*)&Qs[row*FST + c4] = v;
    }

    float m_i[4], l_i[4], o[4][4];
    #pragma unroll
    for (int ii = 0; ii < 4; ii++) {
        m_i[ii] = -1e30f;
        l_i[ii] = 0.f;
        #pragma unroll
        for (int jj = 0; jj < 4; jj++) o[ii][jj] = 0.f;
    }

    for (int kt = 0; kt <= qt; kt++) {
        __syncthreads();  // previous iteration done reading Ks/Vs/Ps
        const float* Kt = Kb + (size_t)kt*64*HDIM;
        const float* Vt = Vb + (size_t)kt*64*HDIM;
        #pragma unroll
        for (int i = 0; i < 4; i++) {
            int idx = tid + i*256;
            int row = idx >> 4;            // key index
            int c4  = (idx & 15) << 2;     // d
            float4 kv = *(const float4*)(Kt + row*HDIM + c4);
            KsT[(c4+0)*FST + row] = kv.x;
            KsT[(c4+1)*FST + row] = kv.y;
            KsT[(c4+2)*FST + row] = kv.z;
            KsT[(c4+3)*FST + row] = kv.w;
            float4 vv = *(const float4*)(Vt + row*HDIM + c4);
            *(float4*)&Vs[row*FST + c4] = vv;
        }
        __syncthreads();

        // S = (Q*scale) @ K^T  (64x64 tile, 4x4 per thread)
        float s[4][4];
        #pragma unroll
        for (int ii = 0; ii < 4; ii++)
            #pragma unroll
            for (int jj = 0; jj < 4; jj++) s[ii][jj] = 0.f;

        #pragma unroll
        for (int d = 0; d < HDIM; d += 4) {
            float qq[4][4], kk[4][4];
            #pragma unroll
            for (int ii = 0; ii < 4; ii++) {
                float4 t = *(const float4*)&Qs[(ty*4+ii)*FST + d];
                qq[ii][0]=t.x; qq[ii][1]=t.y; qq[ii][2]=t.z; qq[ii][3]=t.w;
            }
            #pragma unroll
            for (int t4 = 0; t4 < 4; t4++) {
                float4 t = *(const float4*)&KsT[(d+t4)*FST + tx*4];
                kk[t4][0]=t.x; kk[t4][1]=t.y; kk[t4][2]=t.z; kk[t4][3]=t.w;
            }
            #pragma unroll
            for (int ii = 0; ii < 4; ii++)
                #pragma unroll
                for (int jj = 0; jj < 4; jj++)
                    s[ii][jj] += qq[ii][0]*kk[0][jj] + qq[ii][1]*kk[1][jj]
                               + qq[ii][2]*kk[2][jj] + qq[ii][3]*kk[3][jj];
        }

        // Causal mask on diagonal tile (exactly -1e9, like the reference)
        if (kt == qt) {
            #pragma unroll
            for (int ii = 0; ii < 4; ii++)
                #pragma unroll
                for (int jj = 0; jj < 4; jj++)
                    if (tx*4 + jj > ty*4 + ii) s[ii][jj] = -1e9f;
        }

        // Online softmax per row; row spread across 16 consecutive lanes.
        #pragma unroll
        for (int ii = 0; ii < 4; ii++) {
            float mx = fmaxf(fmaxf(s[ii][0], s[ii][1]), fmaxf(s[ii][2], s[ii][3]));
            mx = fmaxf(mx, __shfl_xor_sync(0xffffffffu, mx, 1));
            mx = fmaxf(mx, __shfl_xor_sync(0xffffffffu, mx, 2));
            mx = fmaxf(mx, __shfl_xor_sync(0xffffffffu, mx, 4));
            mx = fmaxf(mx, __shfl_xor_sync(0xffffffffu, mx, 8));
            float mnew = fmaxf(m_i[ii], mx);
            float corr = __expf(m_i[ii] - mnew);
            float rs = 0.f;
            #pragma unroll
            for (int jj = 0; jj < 4; jj++) {
                s[ii][jj] = __expf(s[ii][jj] - mnew);
                rs += s[ii][jj];
            }
            rs += __shfl_xor_sync(0xffffffffu, rs, 1);
            rs += __shfl_xor_sync(0xffffffffu, rs, 2);
            rs += __shfl_xor_sync(0xffffffffu, rs, 4);
            rs += __shfl_xor_sync(0xffffffffu, rs, 8);
            l_i[ii] = l_i[ii]*corr + rs;
            m_i[ii] = mnew;
            #pragma unroll
            for (int jj = 0; jj < 4; jj++) o[ii][jj] *= corr;
            float4 pr; pr.x = s[ii][0]; pr.y = s[ii][1]; pr.z = s[ii][2]; pr.w = s[ii][3];
            *(float4*)&Ps[(ty*4+ii)*FST + tx*4] = pr;
        }
        __syncthreads();  // Ps visible to all

        // O += P @ V  (64x64x64)
        #pragma unroll
        for (int k4 = 0; k4 < 64; k4 += 4) {
            float pp[4][4], vv[4][4];
            #pragma unroll
            for (int ii = 0; ii < 4; ii++) {
                float4 t = *(const float4*)&Ps[(ty*4+ii)*FST + k4];
                pp[ii][0]=t.x; pp[ii][1]=t.y; pp[ii][2]=t.z; pp[ii][3]=t.w;
            }
            #pragma unroll
            for (int t4 = 0; t4 < 4; t4++) {
                float4 t = *(const float4*)&Vs[(k4+t4)*FST + tx*4];
                vv[t4][0]=t.x; vv[t4][1]=t.y; vv[t4][2]=t.z; vv[t4][3]=t.w;
            }
            #pragma unroll
            for (int ii = 0; ii < 4; ii++)
                #pragma unroll
                for (int jj = 0; jj < 4; jj++)
                    o[ii][jj] += pp[ii][0]*vv[0][jj] + pp[ii][1]*vv[1][jj]
                               + pp[ii][2]*vv[2][jj] + pp[ii][3]*vv[3][jj];
        }
    }

    // Normalize and store to [B,H,S,HD]
    #pragma unroll
    for (int ii = 0; ii < 4; ii++) {
        float inv = 1.f / l_i[ii];
        float4 r;
        r.x = o[ii][0]*inv; r.y = o[ii][1]*inv; r.z = o[ii][2]*inv; r.w = o[ii][3]*inv;
        *(float4*)&Y[(size_t)bh*SS*HDIM + (size_t)(qt*64 + ty*4 + ii)*HDIM + tx*4] = r;
    }
}

// ---------------------------------------------------------------------------
extern "C" void kernel_launch(void* const* d_in, const int* in_sizes, int n_in,
                              void* d_out, int out_size) {
    const float* q  = (const float*)d_in[0];
    const float* k  = (const float*)d_in[1];
    const float* v  = (const float*)d_in[2];
    // d_in[3] = mask (int32 tril) — causal structure is implemented directly
    const float* Wq = (const float*)d_in[4];
    const float* bq = (const float*)d_in[5];
    const float* Wk = (const float*)d_in[6];
    const float* bk = (const float*)d_in[7];
    const float* Wv = (const float*)d_in[8];
    const float* bv = (const float*)d_in[9];
    const float* Wo = (const float*)d_in[10];
    const float* bo = (const float*)d_in[11];
    float* out = (float*)d_out;

    float *qh, *kh, *vh, *y;
    cudaGetSymbolAddress((void**)&qh, g_qh);
    cudaGetSymbolAddress((void**)&kh, g_kh);
    cudaGetSymbolAddress((void**)&vh, g_vh);
    cudaGetSymbolAddress((void**)&y,  g_y);

    dim3 ggrid(DD/GBN, (BB*SS)/GBM);   // (8, 32)
    gemm_relu<false, true><<<ggrid, 256>>>(q, Wq, bq, qh, BB*SS, DD, DD);
    gemm_relu<false, true><<<ggrid, 256>>>(k, Wk, bk, kh, BB*SS, DD, DD);
    gemm_relu<false, true><<<ggrid, 256>>>(v, Wv, bv, vh, BB*SS, DD, DD);

    const int flash_smem = 4 * 64 * FST * (int)sizeof(float);  // 69632 B
    cudaFuncSetAttribute(flash_attn, cudaFuncAttributeMaxDynamicSharedMemorySize, flash_smem);
    flash_attn<<<dim3(SS/64, NBH), 256, flash_smem>>>(qh, kh, vh, y);

    gemm_relu<true, false><<<ggrid, 256>>>(y, Wo, bo, out, BB*SS, DD, DD);
}

// round 2
// speedup vs baseline: 1.8401x; 1.8401x over previous
#include <cuda_runtime.h>
#include <cstdint>

#define BB 4
#define SS 1024
#define DD 1024
#define HH 16
#define HDIM 64
#define NBH (BB*HH)

// Scratch (allocation-free): split-head activations [B,H,S,HD]
__device__ float g_qh[NBH*SS*HDIM];
__device__ float g_kh[NBH*SS*HDIM];
__device__ float g_vh[NBH*SS*HDIM];
__device__ float g_y [NBH*SS*HDIM];

__device__ __forceinline__ uint32_t f2tf32(float x) {
    uint32_t u;
    asm("cvt.rna.tf32.f32 %0, %1;" : "=r"(u) : "f"(x));
    return u;
}

// ---------------------------------------------------------------------------
// TF32 tensor-core GEMM + bias + ReLU.
// C[m][n] = relu(sum_k A[m][k]*W[n][k] + bias[n])     (torch Linear)
// BM=BN=128, BK=32, 256 threads (8 warps as 4x2), warp tile 32x64,
// mma.sync.m16n8k8.tf32, cp.async double-buffered smem.
// IN_SPLIT:  A read from [B,H,S,HD] split-head layout (m=b*S+s, k=h*64+hd)
// OUT_SPLIT: C written to [B,H,S,HD] split-head layout (n=h*64+hd)
// ---------------------------------------------------------------------------
#define GBM 128
#define GBN 128
#define GBK 32
#define GBKP 36   // smem k-stride (pad): conflict-free fragment loads
#define TILEF (128*GBKP)

template<bool IN_SPLIT, bool OUT_SPLIT>
__global__ void __launch_bounds__(256, 2) gemm_tf32(
    const float* __restrict__ A, const float* __restrict__ W,
    const float* __restrict__ bias, float* __restrict__ C,
    int M, int N, int K)
{
    extern __shared__ float sm[];
    float* As = sm;              // [2][128][GBKP]
    float* Ws = sm + 2*TILEF;    // [2][128][GBKP]

    const int tid  = threadIdx.x;
    const int lane = tid & 31;
    const int warp = tid >> 5;
    const int wm   = warp & 3;       // 4 warps along M
    const int wn   = warp >> 2;      // 2 warps along N
    const int lr   = lane >> 2;      // 0..7
    const int lc   = lane & 3;       // 0..3
    const int bm   = blockIdx.y * GBM;
    const int bn   = blockIdx.x * GBN;

    float acc[2][8][4];
    #pragma unroll
    for (int mi = 0; mi < 2; mi++)
        #pragma unroll
        for (int ni = 0; ni < 8; ni++)
            #pragma unroll
            for (int r = 0; r < 4; r++) acc[mi][ni][r] = 0.f;

    uint32_t smem_base = (uint32_t)__cvta_generic_to_shared(sm);

    const int nt = K / GBK;

    // tile loader: 128 rows x 32 floats for A and W, 4 float4 per thread each
    auto load_tile = [&](int k0, int buf) {
        #pragma unroll
        for (int i = 0; i < 4; i++) {
            int idx = i*256 + tid;
            int row = idx >> 3;            // 0..127
            int kc  = (idx & 7) << 2;      // 0,4,...,28
            const float* srcA;
            if (IN_SPLIT) {
                int gm = bm + row, gk = k0 + kc;
                srcA = A + ((size_t)((gm >> 10)*HH + (gk >> 6)))*(SS*HDIM)
                         + (size_t)(gm & 1023)*HDIM + (gk & 63);
            } else {
                srcA = A + (size_t)(bm + row)*K + k0 + kc;
            }
            uint32_t dA = smem_base + (uint32_t)((buf*TILEF + row*GBKP + kc) * 4);
            asm volatile("cp.async.cg.shared.global [%0], [%1], 16;" :: "r"(dA), "l"(srcA));

            const float* srcW = W + (size_t)(bn + row)*K + k0 + kc;
            uint32_t dW = smem_base + (uint32_t)((2*TILEF + buf*TILEF + row*GBKP + kc) * 4);
            asm volatile("cp.async.cg.shared.global [%0], [%1], 16;" :: "r"(dW), "l"(srcW));
        }
        asm volatile("cp.async.commit_group;");
    };

    load_tile(0, 0);

    for (int kt = 0; kt < nt; kt++) {
        asm volatile("cp.async.wait_group 0;");
        __syncthreads();
        if (kt + 1 < nt) load_tile((kt+1)*GBK, (kt+1) & 1);

        const float* Ab = As + (kt & 1)*TILEF;
        const float* Wb = Ws + (kt & 1)*TILEF;

        #pragma unroll
        for (int ks = 0; ks < 4; ks++) {
            const int k0 = ks*8;
            uint32_t a[2][4], b[8][2];
            #pragma unroll
            for (int mi = 0; mi < 2; mi++) {
                int r = wm*32 + mi*16 + lr;
                a[mi][0] = f2tf32(Ab[ r     *GBKP + k0 + lc    ]);
                a[mi][1] = f2tf32(Ab[(r + 8)*GBKP + k0 + lc    ]);
                a[mi][2] = f2tf32(Ab[ r     *GBKP + k0 + lc + 4]);
                a[mi][3] = f2tf32(Ab[(r + 8)*GBKP + k0 + lc + 4]);
            }
            #pragma unroll
            for (int ni = 0; ni < 8; ni++) {
                int c = wn*64 + ni*8 + lr;
                b[ni][0] = f2tf32(Wb[c*GBKP + k0 + lc    ]);
                b[ni][1] = f2tf32(Wb[c*GBKP + k0 + lc + 4]);
            }
            #pragma unroll
            for (int mi = 0; mi < 2; mi++)
                #pragma unroll
                for (int ni = 0; ni < 8; ni++)
                    asm volatile(
                        "mma.sync.aligned.m16n8k8.row.col.f32.tf32.tf32.f32 "
                        "{%0,%1,%2,%3}, {%4,%5,%6,%7}, {%8,%9}, {%0,%1,%2,%3};"
                        : "+f"(acc[mi][ni][0]), "+f"(acc[mi][ni][1]),
                          "+f"(acc[mi][ni][2]), "+f"(acc[mi][ni][3])
                        : "r"(a[mi][0]), "r"(a[mi][1]), "r"(a[mi][2]), "r"(a[mi][3]),
                          "r"(b[ni][0]), "r"(b[ni][1]));
        }
        __syncthreads();
    }

    // Epilogue: bias + ReLU, optional split-head remap. Rows lr / lr+8, col pairs.
    #pragma unroll
    for (int mi = 0; mi < 2; mi++) {
        #pragma unroll
        for (int ni = 0; ni < 8; ni++) {
            int m = bm + wm*32 + mi*16 + lr;
            int n = bn + wn*64 + ni*8 + 2*lc;
            float2 bv = *(const float2*)(bias + n);
            float2 r0, r1;
            r0.x = fmaxf(acc[mi][ni][0] + bv.x, 0.f);
            r0.y = fmaxf(acc[mi][ni][1] + bv.y, 0.f);
            r1.x = fmaxf(acc[mi][ni][2] + bv.x, 0.f);
            r1.y = fmaxf(acc[mi][ni][3] + bv.y, 0.f);
            if (OUT_SPLIT) {
                size_t head = (size_t)((m >> 10)*HH + (n >> 6))*(SS*HDIM) + (n & 63);
                *(float2*)(C + head + (size_t)( m    & 1023)*HDIM) = r0;
                *(float2*)(C + head + (size_t)((m+8) & 1023)*HDIM) = r1;
            } else {
                *(float2*)(C + (size_t)m*N + n)     = r0;
                *(float2*)(C + (size_t)(m+8)*N + n) = r1;
            }
        }
    }
}

// ---------------------------------------------------------------------------
// Causal flash attention, fp32 (unchanged from round 1).
// ---------------------------------------------------------------------------
#define FST 68   // smem row stride

__global__ void __launch_bounds__(256) flash_attn(
    const float* __restrict__ Q, const float* __restrict__ K,
    const float* __restrict__ V, float* __restrict__ Y)
{
    extern __shared__ float smf[];
    float* Qs  = smf;                 // [64][FST]  (row = query, col = d)
    float* KsT = Qs  + 64*FST;        // [64][FST]  (row = d, col = key)  TRANSPOSED
    float* Vs  = KsT + 64*FST;        // [64][FST]  (row = key, col = d)
    float* Ps  = Vs  + 64*FST;        // [64][FST]  (row = query, col = key)

    const int tid = threadIdx.x;
    const int tx = tid & 15;
    const int ty = tid >> 4;
    const int qt = blockIdx.x;        // query tile (64 rows)
    const int bh = blockIdx.y;

    const float* Qb = Q + (size_t)bh*SS*HDIM + (size_t)qt*64*HDIM;
    const float* Kb = K + (size_t)bh*SS*HDIM;
    const float* Vb = V + (size_t)bh*SS*HDIM;

    #pragma unroll
    for (int i = 0; i < 4; i++) {
        int idx = tid + i*256;
        int row = idx >> 4;
        int c4  = (idx & 15) << 2;
        float4 v = *(const float4*)(Qb + row*HDIM + c4);
        v.x *= 0.125f; v.y *= 0.125f; v.z *= 0.125f; v.w *= 0.125f;
        *(float4*)&Qs[row*FST + c4] = v;
    }

    float m_i[4], l_i[4], o[4][4];
    #pragma unroll
    for (int ii = 0; ii < 4; ii++) {
        m_i[ii] = -1e30f;
        l_i[ii] = 0.f;
        #pragma unroll
        for (int jj = 0; jj < 4; jj++) o[ii][jj] = 0.f;
    }

    for (int kt = 0; kt <= qt; kt++) {
        __syncthreads();
        const float* Kt = Kb + (size_t)kt*64*HDIM;
        const float* Vt = Vb + (size_t)kt*64*HDIM;
        #pragma unroll
        for (int i = 0; i < 4; i++) {
            int idx = tid + i*256;
            int row = idx >> 4;
            int c4  = (idx & 15) << 2;
            float4 kv = *(const float4*)(Kt + row*HDIM + c4);
            KsT[(c4+0)*FST + row] = kv.x;
            KsT[(c4+1)*FST + row] = kv.y;
            KsT[(c4+2)*FST + row] = kv.z;
            KsT[(c4+3)*FST + row] = kv.w;
            float4 vv = *(const float4*)(Vt + row*HDIM + c4);
            *(float4*)&Vs[row*FST + c4] = vv;
        }
        __syncthreads();

        float s[4][4];
        #pragma unroll
        for (int ii = 0; ii < 4; ii++)
            #pragma unroll
            for (int jj = 0; jj < 4; jj++) s[ii][jj] = 0.f;

        #pragma unroll
        for (int d = 0; d < HDIM; d += 4) {
            float qq[4][4], kk[4][4];
            #pragma unroll
            for (int ii = 0; ii < 4; ii++) {
                float4 t = *(const float4*)&Qs[(ty*4+ii)*FST + d];
                qq[ii][0]=t.x; qq[ii][1]=t.y; qq[ii][2]=t.z; qq[ii][3]=t.w;
            }
            #pragma unroll
            for (int t4 = 0; t4 < 4; t4++) {
                float4 t = *(const float4*)&KsT[(d+t4)*FST + tx*4];
                kk[t4][0]=t.x; kk[t4][1]=t.y; kk[t4][2]=t.z; kk[t4][3]=t.w;
            }
            #pragma unroll
            for (int ii = 0; ii < 4; ii++)
                #pragma unroll
                for (int jj = 0; jj < 4; jj++)
                    s[ii][jj] += qq[ii][0]*kk[0][jj] + qq[ii][1]*kk[1][jj]
                               + qq[ii][2]*kk[2][jj] + qq[ii][3]*kk[3][jj];
        }

        if (kt == qt) {
            #pragma unroll
            for (int ii = 0; ii < 4; ii++)
                #pragma unroll
                for (int jj = 0; jj < 4; jj++)
                    if (tx*4 + jj > ty*4 + ii) s[ii][jj] = -1e9f;
        }

        #pragma unroll
        for (int ii = 0; ii < 4; ii++) {
            float mx = fmaxf(fmaxf(s[ii][0], s[ii][1]), fmaxf(s[ii][2], s[ii][3]));
            mx = fmaxf(mx, __shfl_xor_sync(0xffffffffu, mx, 1));
            mx = fmaxf(mx, __shfl_xor_sync(0xffffffffu, mx, 2));
            mx = fmaxf(mx, __shfl_xor_sync(0xffffffffu, mx, 4));
            mx = fmaxf(mx, __shfl_xor_sync(0xffffffffu, mx, 8));
            float mnew = fmaxf(m_i[ii], mx);
            float corr = __expf(m_i[ii] - mnew);
            float rs = 0.f;
            #pragma unroll
            for (int jj = 0; jj < 4; jj++) {
                s[ii][jj] = __expf(s[ii][jj] - mnew);
                rs += s[ii][jj];
            }
            rs += __shfl_xor_sync(0xffffffffu, rs, 1);
            rs += __shfl_xor_sync(0xffffffffu, rs, 2);
            rs += __shfl_xor_sync(0xffffffffu, rs, 4);
            rs += __shfl_xor_sync(0xffffffffu, rs, 8);
            l_i[ii] = l_i[ii]*corr + rs;
            m_i[ii] = mnew;
            #pragma unroll
            for (int jj = 0; jj < 4; jj++) o[ii][jj] *= corr;
            float4 pr; pr.x = s[ii][0]; pr.y = s[ii][1]; pr.z = s[ii][2]; pr.w = s[ii][3];
            *(float4*)&Ps[(ty*4+ii)*FST + tx*4] = pr;
        }
        __syncthreads();

        #pragma unroll
        for (int k4 = 0; k4 < 64; k4 += 4) {
            float pp[4][4], vv[4][4];
            #pragma unroll
            for (int ii = 0; ii < 4; ii++) {
                float4 t = *(const float4*)&Ps[(ty*4+ii)*FST + k4];
                pp[ii][0]=t.x; pp[ii][1]=t.y; pp[ii][2]=t.z; pp[ii][3]=t.w;
            }
            #pragma unroll
            for (int t4 = 0; t4 < 4; t4++) {
                float4 t = *(const float4*)&Vs[(k4+t4)*FST + tx*4];
                vv[t4][0]=t.x; vv[t4][1]=t.y; vv[t4][2]=t.z; vv[t4][3]=t.w;
            }
            #pragma unroll
            for (int ii = 0; ii < 4; ii++)
                #pragma unroll
                for (int jj = 0; jj < 4; jj++)
                    o[ii][jj] += pp[ii][0]*vv[0][jj] + pp[ii][1]*vv[1][jj]
                               + pp[ii][2]*vv[2][jj] + pp[ii][3]*vv[3][jj];
        }
    }

    #pragma unroll
    for (int ii = 0; ii < 4; ii++) {
        float inv = 1.f / l_i[ii];
        float4 r;
        r.x = o[ii][0]*inv; r.y = o[ii][1]*inv; r.z = o[ii][2]*inv; r.w = o[ii][3]*inv;
        *(float4*)&Y[(size_t)bh*SS*HDIM + (size_t)(qt*64 + ty*4 + ii)*HDIM + tx*4] = r;
    }
}

// ---------------------------------------------------------------------------
extern "C" void kernel_launch(void* const* d_in, const int* in_sizes, int n_in,
                              void* d_out, int out_size) {
    const float* q  = (const float*)d_in[0];
    const float* k  = (const float*)d_in[1];
    const float* v  = (const float*)d_in[2];
    // d_in[3] = mask (int32 tril) — causal structure implemented directly
    const float* Wq = (const float*)d_in[4];
    const float* bq = (const float*)d_in[5];
    const float* Wk = (const float*)d_in[6];
    const float* bk = (const float*)d_in[7];
    const float* Wv = (const float*)d_in[8];
    const float* bv = (const float*)d_in[9];
    const float* Wo = (const float*)d_in[10];
    const float* bo = (const float*)d_in[11];
    float* out = (float*)d_out;

    float *qh, *kh, *vh, *y;
    cudaGetSymbolAddress((void**)&qh, g_qh);
    cudaGetSymbolAddress((void**)&kh, g_kh);
    cudaGetSymbolAddress((void**)&vh, g_vh);
    cudaGetSymbolAddress((void**)&y,  g_y);

    const int gemm_smem = 4 * TILEF * (int)sizeof(float);  // 73728 B
    cudaFuncSetAttribute(gemm_tf32<false,true>,
                         cudaFuncAttributeMaxDynamicSharedMemorySize, gemm_smem);
    cudaFuncSetAttribute(gemm_tf32<true,false>,
                         cudaFuncAttributeMaxDynamicSharedMemorySize, gemm_smem);

    dim3 ggrid(DD/GBN, (BB*SS)/GBM);   // (8, 32)
    gemm_tf32<false, true><<<ggrid, 256, gemm_smem>>>(q, Wq, bq, qh, BB*SS, DD, DD);
    gemm_tf32<false, true><<<ggrid, 256, gemm_smem>>>(k, Wk, bk, kh, BB*SS, DD, DD);
    gemm_tf32<false, true><<<ggrid, 256, gemm_smem>>>(v, Wv, bv, vh, BB*SS, DD, DD);

    const int flash_smem = 4 * 64 * FST * (int)sizeof(float);  // 69632 B
    cudaFuncSetAttribute(flash_attn, cudaFuncAttributeMaxDynamicSharedMemorySize, flash_smem);
    flash_attn<<<dim3(SS/64, NBH), 256, flash_smem>>>(qh, kh, vh, y);

    gemm_tf32<true, false><<<ggrid, 256, gemm_smem>>>(y, Wo, bo, out, BB*SS, DD, DD);
}

// round 3
// speedup vs baseline: 2.6497x; 1.4399x over previous
#include <cuda_runtime.h>
#include <cstdint>

#define BB 4
#define SS 1024
#define DD 1024
#define HH 16
#define HDIM 64
#define NBH (BB*HH)

// Scratch (allocation-free): split-head activations [B,H,S,HD]
__device__ float g_qh[NBH*SS*HDIM];
__device__ float g_kh[NBH*SS*HDIM];
__device__ float g_vh[NBH*SS*HDIM];
__device__ float g_y [NBH*SS*HDIM];

__device__ __forceinline__ uint32_t f2tf32(float x) {
    uint32_t u;
    asm("cvt.rna.tf32.f32 %0, %1;" : "=r"(u) : "f"(x));
    return u;
}

#define MMA_TF32(acc, a0,a1,a2,a3, b0,b1)                                   \
    asm volatile(                                                           \
        "mma.sync.aligned.m16n8k8.row.col.f32.tf32.tf32.f32 "               \
        "{%0,%1,%2,%3}, {%4,%5,%6,%7}, {%8,%9}, {%0,%1,%2,%3};"             \
        : "+f"(acc[0]), "+f"(acc[1]), "+f"(acc[2]), "+f"(acc[3])            \
        : "r"(a0), "r"(a1), "r"(a2), "r"(a3), "r"(b0), "r"(b1))

// ---------------------------------------------------------------------------
// TF32 tensor-core GEMM + bias + ReLU (unchanged from round 2).
// ---------------------------------------------------------------------------
#define GBM 128
#define GBN 128
#define GBK 32
#define GBKP 36
#define TILEF (128*GBKP)

template<bool IN_SPLIT, bool OUT_SPLIT>
__global__ void __launch_bounds__(256, 2) gemm_tf32(
    const float* __restrict__ A, const float* __restrict__ W,
    const float* __restrict__ bias, float* __restrict__ C,
    int M, int N, int K)
{
    extern __shared__ float sm[];
    float* As = sm;
    float* Ws = sm + 2*TILEF;

    const int tid  = threadIdx.x;
    const int lane = tid & 31;
    const int warp = tid >> 5;
    const int wm   = warp & 3;
    const int wn   = warp >> 2;
    const int lr   = lane >> 2;
    const int lc   = lane & 3;
    const int bm   = blockIdx.y * GBM;
    const int bn   = blockIdx.x * GBN;

    float acc[2][8][4];
    #pragma unroll
    for (int mi = 0; mi < 2; mi++)
        #pragma unroll
        for (int ni = 0; ni < 8; ni++)
            #pragma unroll
            for (int r = 0; r < 4; r++) acc[mi][ni][r] = 0.f;

    uint32_t smem_base = (uint32_t)__cvta_generic_to_shared(sm);
    const int nt = K / GBK;

    auto load_tile = [&](int k0, int buf) {
        #pragma unroll
        for (int i = 0; i < 4; i++) {
            int idx = i*256 + tid;
            int row = idx >> 3;
            int kc  = (idx & 7) << 2;
            const float* srcA;
            if (IN_SPLIT) {
                int gm = bm + row, gk = k0 + kc;
                srcA = A + ((size_t)((gm >> 10)*HH + (gk >> 6)))*(SS*HDIM)
                         + (size_t)(gm & 1023)*HDIM + (gk & 63);
            } else {
                srcA = A + (size_t)(bm + row)*K + k0 + kc;
            }
            uint32_t dA = smem_base + (uint32_t)((buf*TILEF + row*GBKP + kc) * 4);
            asm volatile("cp.async.cg.shared.global [%0], [%1], 16;" :: "r"(dA), "l"(srcA));

            const float* srcW = W + (size_t)(bn + row)*K + k0 + kc;
            uint32_t dW = smem_base + (uint32_t)((2*TILEF + buf*TILEF + row*GBKP + kc) * 4);
            asm volatile("cp.async.cg.shared.global [%0], [%1], 16;" :: "r"(dW), "l"(srcW));
        }
        asm volatile("cp.async.commit_group;");
    };

    load_tile(0, 0);

    for (int kt = 0; kt < nt; kt++) {
        asm volatile("cp.async.wait_group 0;");
        __syncthreads();
        if (kt + 1 < nt) load_tile((kt+1)*GBK, (kt+1) & 1);

        const float* Ab = As + (kt & 1)*TILEF;
        const float* Wb = Ws + (kt & 1)*TILEF;

        #pragma unroll
        for (int ks = 0; ks < 4; ks++) {
            const int k0 = ks*8;
            uint32_t a[2][4], b[8][2];
            #pragma unroll
            for (int mi = 0; mi < 2; mi++) {
                int r = wm*32 + mi*16 + lr;
                a[mi][0] = f2tf32(Ab[ r     *GBKP + k0 + lc    ]);
                a[mi][1] = f2tf32(Ab[(r + 8)*GBKP + k0 + lc    ]);
                a[mi][2] = f2tf32(Ab[ r     *GBKP + k0 + lc + 4]);
                a[mi][3] = f2tf32(Ab[(r + 8)*GBKP + k0 + lc + 4]);
            }
            #pragma unroll
            for (int ni = 0; ni < 8; ni++) {
                int c = wn*64 + ni*8 + lr;
                b[ni][0] = f2tf32(Wb[c*GBKP + k0 + lc    ]);
                b[ni][1] = f2tf32(Wb[c*GBKP + k0 + lc + 4]);
            }
            #pragma unroll
            for (int mi = 0; mi < 2; mi++)
                #pragma unroll
                for (int ni = 0; ni < 8; ni++)
                    MMA_TF32(acc[mi][ni],
                             a[mi][0], a[mi][1], a[mi][2], a[mi][3],
                             b[ni][0], b[ni][1]);
        }
        __syncthreads();
    }

    #pragma unroll
    for (int mi = 0; mi < 2; mi++) {
        #pragma unroll
        for (int ni = 0; ni < 8; ni++) {
            int m = bm + wm*32 + mi*16 + lr;
            int n = bn + wn*64 + ni*8 + 2*lc;
            float2 bv = *(const float2*)(bias + n);
            float2 r0, r1;
            r0.x = fmaxf(acc[mi][ni][0] + bv.x, 0.f);
            r0.y = fmaxf(acc[mi][ni][1] + bv.y, 0.f);
            r1.x = fmaxf(acc[mi][ni][2] + bv.x, 0.f);
            r1.y = fmaxf(acc[mi][ni][3] + bv.y, 0.f);
            if (OUT_SPLIT) {
                size_t head = (size_t)((m >> 10)*HH + (n >> 6))*(SS*HDIM) + (n & 63);
                *(float2*)(C + head + (size_t)( m    & 1023)*HDIM) = r0;
                *(float2*)(C + head + (size_t)((m+8) & 1023)*HDIM) = r1;
            } else {
                *(float2*)(C + (size_t)m*N + n)     = r0;
                *(float2*)(C + (size_t)(m+8)*N + n) = r1;
            }
        }
    }
}

// ---------------------------------------------------------------------------
// Causal flash attention with TF32 tensor cores.
// 1 block = (64-query tile, b*h). 128 threads / 4 warps; warp owns 16 q rows.
// Q fragments held in registers across all key tiles. K/V double-buffered
// via cp.async. P staged through warp-private smem rows (no cross-warp sync).
// Smem strides: KST=68, VST=72, PST=68 -> all fragment LDS conflict-free.
// ---------------------------------------------------------------------------
#define KST 68
#define VST 72
#define PST 68
#define KTILE (64*KST)
#define VTILE (64*VST)

__global__ void __launch_bounds__(128) flash_attn_tf32(
    const float* __restrict__ Q, const float* __restrict__ K,
    const float* __restrict__ V, float* __restrict__ Y)
{
    extern __shared__ float smf[];
    float* Ks = smf;                 // [2][64][KST]
    float* Vs = Ks + 2*KTILE;        // [2][64][VST]
    float* Ps = Vs + 2*VTILE;        // [64][PST]  (also Q staging)

    const int tid  = threadIdx.x;
    const int lane = tid & 31;
    const int warp = tid >> 5;
    const int lr   = lane >> 2;     // 0..7
    const int lc   = lane & 3;      // 0..3
    const int qt   = blockIdx.x;
    const int bh   = blockIdx.y;
    const int r0   = warp*16 + lr;  // local row 0 (row 1 = r0+8)

    const float* Qb = Q + (size_t)bh*SS*HDIM + (size_t)qt*64*HDIM;
    const float* Kb = K + (size_t)bh*SS*HDIM;
    const float* Vb = V + (size_t)bh*SS*HDIM;

    // ---- Stage Q (scaled) into Ps, convert to persistent TF32 fragments ----
    #pragma unroll
    for (int i = 0; i < 8; i++) {
        int idx = tid + i*128;
        int row = idx >> 4;
        int c4  = (idx & 15) << 2;
        float4 v = *(const float4*)(Qb + row*HDIM + c4);
        v.x *= 0.125f; v.y *= 0.125f; v.z *= 0.125f; v.w *= 0.125f;
        *(float4*)&Ps[row*PST + c4] = v;
    }
    __syncthreads();

    uint32_t qf[8][4];
    #pragma unroll
    for (int ks = 0; ks < 8; ks++) {
        int k0 = ks*8;
        qf[ks][0] = f2tf32(Ps[ r0     *PST + k0 + lc    ]);
        qf[ks][1] = f2tf32(Ps[(r0 + 8)*PST + k0 + lc    ]);
        qf[ks][2] = f2tf32(Ps[ r0     *PST + k0 + lc + 4]);
        qf[ks][3] = f2tf32(Ps[(r0 + 8)*PST + k0 + lc + 4]);
    }
    __syncthreads();   // all warps done reading Q staging before Ps reuse

    uint32_t smem_base = (uint32_t)__cvta_generic_to_shared(smf);

    auto load_kv = [&](int kt, int buf) {
        const float* Kt = Kb + (size_t)kt*64*HDIM;
        const float* Vt = Vb + (size_t)kt*64*HDIM;
        #pragma unroll
        for (int i = 0; i < 8; i++) {
            int idx = tid + i*128;
            int row = idx >> 4;
            int c4  = (idx & 15) << 2;
            uint32_t dK = smem_base + (uint32_t)((buf*KTILE + row*KST + c4)*4);
            asm volatile("cp.async.cg.shared.global [%0], [%1], 16;"
                         :: "r"(dK), "l"(Kt + row*HDIM + c4));
            uint32_t dV = smem_base + (uint32_t)((2*KTILE + buf*VTILE + row*VST + c4)*4);
            asm volatile("cp.async.cg.shared.global [%0], [%1], 16;"
                         :: "r"(dV), "l"(Vt + row*HDIM + c4));
        }
        asm volatile("cp.async.commit_group;");
    };

    load_kv(0, 0);

    float m0 = -1e30f, m1 = -1e30f, l0 = 0.f, l1 = 0.f;
    float o[8][4];
    #pragma unroll
    for (int ni = 0; ni < 8; ni++)
        #pragma unroll
        for (int r = 0; r < 4; r++) o[ni][r] = 0.f;

    for (int kt = 0; kt <= qt; kt++) {
        const int buf = kt & 1;
        asm volatile("cp.async.wait_group 0;");
        __syncthreads();                       // K/V[buf] ready; prev reads done
        if (kt < qt) load_kv(kt + 1, buf ^ 1);

        const float* Kt = Ks + buf*KTILE;
        const float* Vt = Vs + buf*VTILE;

        // ---- S = (Q*scale) @ K^T ----
        float s[8][4];
        #pragma unroll
        for (int ni = 0; ni < 8; ni++)
            #pragma unroll
            for (int r = 0; r < 4; r++) s[ni][r] = 0.f;

        #pragma unroll
        for (int ks = 0; ks < 8; ks++) {
            int k0 = ks*8;
            #pragma unroll
            for (int ni = 0; ni < 8; ni++) {
                uint32_t b0 = f2tf32(Kt[(ni*8 + lr)*KST + k0 + lc    ]);
                uint32_t b1 = f2tf32(Kt[(ni*8 + lr)*KST + k0 + lc + 4]);
                MMA_TF32(s[ni], qf[ks][0], qf[ks][1], qf[ks][2], qf[ks][3], b0, b1);
            }
        }

        // ---- causal mask on diagonal tile (exact -1e9, as reference) ----
        if (kt == qt) {
            #pragma unroll
            for (int ni = 0; ni < 8; ni++) {
                int c = ni*8 + 2*lc;
                if (c     > r0    ) s[ni][0] = -1e9f;
                if (c + 1 > r0    ) s[ni][1] = -1e9f;
                if (c     > r0 + 8) s[ni][2] = -1e9f;
                if (c + 1 > r0 + 8) s[ni][3] = -1e9f;
            }
        }

        // ---- online softmax (rows r0, r0+8; cols spread over 4 lanes) ----
        float mx0 = -1e30f, mx1 = -1e30f;
        #pragma unroll
        for (int ni = 0; ni < 8; ni++) {
            mx0 = fmaxf(mx0, fmaxf(s[ni][0], s[ni][1]));
            mx1 = fmaxf(mx1, fmaxf(s[ni][2], s[ni][3]));
        }
        mx0 = fmaxf(mx0, __shfl_xor_sync(0xffffffffu, mx0, 1));
        mx0 = fmaxf(mx0, __shfl_xor_sync(0xffffffffu, mx0, 2));
        mx1 = fmaxf(mx1, __shfl_xor_sync(0xffffffffu, mx1, 1));
        mx1 = fmaxf(mx1, __shfl_xor_sync(0xffffffffu, mx1, 2));

        float mn0 = fmaxf(m0, mx0), mn1 = fmaxf(m1, mx1);
        float c0 = __expf(m0 - mn0), c1 = __expf(m1 - mn1);
        float rs0 = 0.f, rs1 = 0.f;
        #pragma unroll
        for (int ni = 0; ni < 8; ni++) {
            s[ni][0] = __expf(s[ni][0] - mn0);
            s[ni][1] = __expf(s[ni][1] - mn0);
            s[ni][2] = __expf(s[ni][2] - mn1);
            s[ni][3] = __expf(s[ni][3] - mn1);
            rs0 += s[ni][0] + s[ni][1];
            rs1 += s[ni][2] + s[ni][3];
        }
        rs0 += __shfl_xor_sync(0xffffffffu, rs0, 1);
        rs0 += __shfl_xor_sync(0xffffffffu, rs0, 2);
        rs1 += __shfl_xor_sync(0xffffffffu, rs1, 1);
        rs1 += __shfl_xor_sync(0xffffffffu, rs1, 2);
        l0 = l0*c0 + rs0;  m0 = mn0;
        l1 = l1*c1 + rs1;  m1 = mn1;

        #pragma unroll
        for (int ni = 0; ni < 8; ni++) {
            o[ni][0] *= c0;  o[ni][1] *= c0;
            o[ni][2] *= c1;  o[ni][3] *= c1;
            float2 p0; p0.x = s[ni][0]; p0.y = s[ni][1];
            float2 p1; p1.x = s[ni][2]; p1.y = s[ni][3];
            *(float2*)&Ps[ r0     *PST + ni*8 + 2*lc] = p0;
            *(float2*)&Ps[(r0 + 8)*PST + ni*8 + 2*lc] = p1;
        }
        __syncwarp();   // Ps rows are warp-private; STS->LDS exchange in-warp

        // ---- O += P @ V ----
        #pragma unroll
        for (int ks = 0; ks < 8; ks++) {
            int k0 = ks*8;
            uint32_t a0 = f2tf32(Ps[ r0     *PST + k0 + lc    ]);
            uint32_t a1 = f2tf32(Ps[(r0 + 8)*PST + k0 + lc    ]);
            uint32_t a2 = f2tf32(Ps[ r0     *PST + k0 + lc + 4]);
            uint32_t a3 = f2tf32(Ps[(r0 + 8)*PST + k0 + lc + 4]);
            #pragma unroll
            for (int ni = 0; ni < 8; ni++) {
                uint32_t b0 = f2tf32(Vt[(k0 + lc    )*VST + ni*8 + lr]);
                uint32_t b1 = f2tf32(Vt[(k0 + lc + 4)*VST + ni*8 + lr]);
                MMA_TF32(o[ni], a0, a1, a2, a3, b0, b1);
            }
        }
    }

    // ---- normalize, store to [B,H,S,HD] ----
    float inv0 = 1.f / l0, inv1 = 1.f / l1;
    float* Yb = Y + (size_t)bh*SS*HDIM + (size_t)qt*64*HDIM;
    #pragma unroll
    for (int ni = 0; ni < 8; ni++) {
        int c = ni*8 + 2*lc;
        float2 y0; y0.x = o[ni][0]*inv0; y0.y = o[ni][1]*inv0;
        float2 y1; y1.x = o[ni][2]*inv1; y1.y = o[ni][3]*inv1;
        *(float2*)(Yb + (size_t) r0     *HDIM + c) = y0;
        *(float2*)(Yb + (size_t)(r0 + 8)*HDIM + c) = y1;
    }
}

// ---------------------------------------------------------------------------
extern "C" void kernel_launch(void* const* d_in, const int* in_sizes, int n_in,
                              void* d_out, int out_size) {
    const float* q  = (const float*)d_in[0];
    const float* k  = (const float*)d_in[1];
    const float* v  = (const float*)d_in[2];
    // d_in[3] = mask (int32 tril) — causal structure implemented directly
    const float* Wq = (const float*)d_in[4];
    const float* bq = (const float*)d_in[5];
    const float* Wk = (const float*)d_in[6];
    const float* bk = (const float*)d_in[7];
    const float* Wv = (const float*)d_in[8];
    const float* bv = (const float*)d_in[9];
    const float* Wo = (const float*)d_in[10];
    const float* bo = (const float*)d_in[11];
    float* out = (float*)d_out;

    float *qh, *kh, *vh, *y;
    cudaGetSymbolAddress((void**)&qh, g_qh);
    cudaGetSymbolAddress((void**)&kh, g_kh);
    cudaGetSymbolAddress((void**)&vh, g_vh);
    cudaGetSymbolAddress((void**)&y,  g_y);

    const int gemm_smem = 4 * TILEF * (int)sizeof(float);  // 73728 B
    cudaFuncSetAttribute(gemm_tf32<false,true>,
                         cudaFuncAttributeMaxDynamicSharedMemorySize, gemm_smem);
    cudaFuncSetAttribute(gemm_tf32<true,false>,
                         cudaFuncAttributeMaxDynamicSharedMemorySize, gemm_smem);

    dim3 ggrid(DD/GBN, (BB*SS)/GBM);   // (8, 32)
    gemm_tf32<false, true><<<ggrid, 256, gemm_smem>>>(q, Wq, bq, qh, BB*SS, DD, DD);
    gemm_tf32<false, true><<<ggrid, 256, gemm_smem>>>(k, Wk, bk, kh, BB*SS, DD, DD);
    gemm_tf32<false, true><<<ggrid, 256, gemm_smem>>>(v, Wv, bv, vh, BB*SS, DD, DD);

    const int flash_smem = (2*KTILE + 2*VTILE + 64*PST) * (int)sizeof(float); // 89088 B
    cudaFuncSetAttribute(flash_attn_tf32,
                         cudaFuncAttributeMaxDynamicSharedMemorySize, flash_smem);
    flash_attn_tf32<<<dim3(SS/64, NBH), 128, flash_smem>>>(qh, kh, vh, y);

    gemm_tf32<true, false><<<ggrid, 256, gemm_smem>>>(y, Wo, bo, out, BB*SS, DD, DD);
}

// round 4
// speedup vs baseline: 5.5545x; 2.0963x over previous
#include <cuda_runtime.h>
#include <cuda_fp16.h>
#include <cstdint>

#define BB 4
#define SS 1024
#define DD 1024
#define HH 16
#define HDIM 64
#define NBH (BB*HH)

// fp16 scratch (allocation-free)
__device__ __align__(16) __half g_q16 [BB*SS*DD];
__device__ __align__(16) __half g_k16 [BB*SS*DD];
__device__ __align__(16) __half g_v16 [BB*SS*DD];
__device__ __align__(16) __half g_wq16[DD*DD];
__device__ __align__(16) __half g_wk16[DD*DD];
__device__ __align__(16) __half g_wv16[DD*DD];
__device__ __align__(16) __half g_wo16[DD*DD];
__device__ __align__(16) __half g_qh16[NBH*SS*HDIM];   // [bh][q][d]
__device__ __align__(16) __half g_kh16[NBH*SS*HDIM];   // [bh][key][d]
__device__ __align__(16) __half g_vht16[NBH*SS*HDIM];  // [bh][d][key]  TRANSPOSED
__device__ __align__(16) __half g_y16 [NBH*SS*HDIM];   // [bh][q][d]

#define MMA_F16(acc, a0,a1,a2,a3, b0,b1)                                    \
    asm volatile(                                                           \
        "mma.sync.aligned.m16n8k16.row.col.f32.f16.f16.f32 "                \
        "{%0,%1,%2,%3}, {%4,%5,%6,%7}, {%8,%9}, {%0,%1,%2,%3};"             \
        : "+f"(acc[0]), "+f"(acc[1]), "+f"(acc[2]), "+f"(acc[3])            \
        : "r"(a0), "r"(a1), "r"(a2), "r"(a3), "r"(b0), "r"(b1))

__device__ __forceinline__ uint32_t ldsm_u32(const __half* p) {
    return *(const uint32_t*)p;
}

// ---------------------------------------------------------------------------
// Fused fp32 -> fp16 conversion for 7 tensors in one launch.
// ---------------------------------------------------------------------------
struct CvtArgs {
    const float* src[7];
    __half*      dst[7];
    int          n[7];
};

__global__ void __launch_bounds__(256) convert_all(CvtArgs args) {
    const int t = blockIdx.y;
    const int n = args.n[t];
    int base = (blockIdx.x * 256 + threadIdx.x) * 8;
    if (base >= n) return;
    const float4* s = (const float4*)(args.src[t] + base);
    float4 f0 = s[0], f1 = s[1];
    __half2 h0 = __floats2half2_rn(f0.x, f0.y);
    __half2 h1 = __floats2half2_rn(f0.z, f0.w);
    __half2 h2 = __floats2half2_rn(f1.x, f1.y);
    __half2 h3 = __floats2half2_rn(f1.z, f1.w);
    uint4 o;
    o.x = *(uint32_t*)&h0; o.y = *(uint32_t*)&h1;
    o.z = *(uint32_t*)&h2; o.w = *(uint32_t*)&h3;
    *(uint4*)(args.dst[t] + base) = o;
}

// ---------------------------------------------------------------------------
// FP16 tensor-core GEMM + bias + ReLU.
// C[m][n] = relu(sum_k A[m][k]*W[n][k] + bias[n]),  A/W fp16, accum fp32.
// BM=BN=128, BK=64, 256 threads (8 warps 4x2), warp tile 32x64, m16n8k16.
// OUT_MODE: 0 = fp32 row-major, 1 = fp16 split-head [bh][s][d],
//           2 = fp16 split-head transposed [bh][d][s]
// IN_SPLIT: A read from fp16 [bh][s][d] split-head layout.
// smem stride 72 halves (=36 words): frag LDS word = lr*4+lc mod 32 -> no conflicts.
// ---------------------------------------------------------------------------
#define GBK 64
#define HST 72
#define HTILE (128*HST)   // halves per buffer per matrix

template<bool IN_SPLIT, int OUT_MODE>
__global__ void __launch_bounds__(256, 2) gemm_h(
    const __half* __restrict__ A, const __half* __restrict__ W,
    const float* __restrict__ bias, void* __restrict__ Cv,
    int M, int N, int K)
{
    extern __shared__ __half smh[];
    __half* As = smh;              // [2][128][HST]
    __half* Ws = smh + 2*HTILE;    // [2][128][HST]

    const int tid  = threadIdx.x;
    const int lane = tid & 31;
    const int warp = tid >> 5;
    const int wm   = warp & 3;
    const int wn   = warp >> 2;
    const int lr   = lane >> 2;
    const int lc   = lane & 3;
    const int bm   = blockIdx.y * 128;
    const int bn   = blockIdx.x * 128;

    float acc[2][8][4];
    #pragma unroll
    for (int mi = 0; mi < 2; mi++)
        #pragma unroll
        for (int ni = 0; ni < 8; ni++)
            #pragma unroll
            for (int r = 0; r < 4; r++) acc[mi][ni][r] = 0.f;

    uint32_t smem_base = (uint32_t)__cvta_generic_to_shared(smh);
    const int nt = K / GBK;

    auto load_tile = [&](int k0, int buf) {
        #pragma unroll
        for (int i = 0; i < 4; i++) {
            int idx  = i*256 + tid;
            int row  = idx >> 3;           // 0..127
            int kc   = (idx & 7) << 3;     // halves 0,8,...,56
            const __half* srcA;
            if (IN_SPLIT) {
                int gm = bm + row, gk = k0 + kc;
                srcA = A + ((size_t)((gm >> 10)*HH + (gk >> 6)))*(SS*HDIM)
                         + (size_t)(gm & 1023)*HDIM + (gk & 63);
            } else {
                srcA = A + (size_t)(bm + row)*K + k0 + kc;
            }
            uint32_t dA = smem_base + (uint32_t)((buf*HTILE + row*HST + kc) * 2);
            asm volatile("cp.async.cg.shared.global [%0], [%1], 16;" :: "r"(dA), "l"(srcA));

            const __half* srcW = W + (size_t)(bn + row)*K + k0 + kc;
            uint32_t dW = smem_base + (uint32_t)((2*HTILE + buf*HTILE + row*HST + kc) * 2);
            asm volatile("cp.async.cg.shared.global [%0], [%1], 16;" :: "r"(dW), "l"(srcW));
        }
        asm volatile("cp.async.commit_group;");
    };

    load_tile(0, 0);

    for (int kt = 0; kt < nt; kt++) {
        asm volatile("cp.async.wait_group 0;");
        __syncthreads();
        if (kt + 1 < nt) load_tile((kt+1)*GBK, (kt+1) & 1);

        const __half* Ab = As + (kt & 1)*HTILE;
        const __half* Wb = Ws + (kt & 1)*HTILE;

        #pragma unroll
        for (int ks = 0; ks < 4; ks++) {
            const int kh = ks*16;          // halves
            uint32_t a[2][4], b[8][2];
            #pragma unroll
            for (int mi = 0; mi < 2; mi++) {
                int r = wm*32 + mi*16 + lr;
                a[mi][0] = ldsm_u32(&Ab[ r     *HST + kh + 2*lc    ]);
                a[mi][1] = ldsm_u32(&Ab[(r + 8)*HST + kh + 2*lc    ]);
                a[mi][2] = ldsm_u32(&Ab[ r     *HST + kh + 2*lc + 8]);
                a[mi][3] = ldsm_u32(&Ab[(r + 8)*HST + kh + 2*lc + 8]);
            }
            #pragma unroll
            for (int ni = 0; ni < 8; ni++) {
                int c = wn*64 + ni*8 + lr;
                b[ni][0] = ldsm_u32(&Wb[c*HST + kh + 2*lc    ]);
                b[ni][1] = ldsm_u32(&Wb[c*HST + kh + 2*lc + 8]);
            }
            #pragma unroll
            for (int mi = 0; mi < 2; mi++)
                #pragma unroll
                for (int ni = 0; ni < 8; ni++)
                    MMA_F16(acc[mi][ni],
                            a[mi][0], a[mi][1], a[mi][2], a[mi][3],
                            b[ni][0], b[ni][1]);
        }
        __syncthreads();
    }

    #pragma unroll
    for (int mi = 0; mi < 2; mi++) {
        #pragma unroll
        for (int ni = 0; ni < 8; ni++) {
            int m = bm + wm*32 + mi*16 + lr;
            int n = bn + wn*64 + ni*8 + 2*lc;
            float2 bv = *(const float2*)(bias + n);
            float v00 = fmaxf(acc[mi][ni][0] + bv.x, 0.f);
            float v01 = fmaxf(acc[mi][ni][1] + bv.y, 0.f);
            float v10 = fmaxf(acc[mi][ni][2] + bv.x, 0.f);
            float v11 = fmaxf(acc[mi][ni][3] + bv.y, 0.f);
            if (OUT_MODE == 0) {
                float* C = (float*)Cv;
                float2 r0; r0.x = v00; r0.y = v01;
                float2 r1; r1.x = v10; r1.y = v11;
                *(float2*)(C + (size_t)m*N + n)     = r0;
                *(float2*)(C + (size_t)(m+8)*N + n) = r1;
            } else if (OUT_MODE == 1) {
                __half* C = (__half*)Cv;
                size_t head = (size_t)((m >> 10)*HH + (n >> 6))*(SS*HDIM) + (n & 63);
                *(__half2*)(C + head + (size_t)( m    & 1023)*HDIM) = __floats2half2_rn(v00, v01);
                *(__half2*)(C + head + (size_t)((m+8) & 1023)*HDIM) = __floats2half2_rn(v10, v11);
            } else {
                __half* C = (__half*)Cv;   // [bh][d][s]
                size_t head = (size_t)((m >> 10)*HH + (n >> 6))*(SS*HDIM);
                size_t drow0 = head + (size_t)(n & 63)*SS;
                size_t drow1 = head + (size_t)((n+1) & 63)*SS;
                C[drow0 + ( m    & 1023)] = __float2half_rn(v00);
                C[drow1 + ( m    & 1023)] = __float2half_rn(v01);
                C[drow0 + ((m+8) & 1023)] = __float2half_rn(v10);
                C[drow1 + ((m+8) & 1023)] = __float2half_rn(v11);
            }
        }
    }
}

// ---------------------------------------------------------------------------
// Causal flash attention, fp16 mma (m16n8k16), fp32 softmax/accum.
// 1 block = (64-query tile, bh). 128 threads / 4 warps; warp owns 16 q rows.
// K [key][d] fp16, V pre-transposed [d][key] fp16 (both cp.async double-buf).
// P staged fp16 in warp-private smem rows. smem stride 72 halves everywhere.
// smem total = 5 * 64*72*2B = 45KB -> up to 4 blocks/SM.
// ---------------------------------------------------------------------------
#define FTILE (64*HST)

__global__ void __launch_bounds__(128, 3) flash_attn_h(
    const __half* __restrict__ Q, const __half* __restrict__ K,
    const __half* __restrict__ V, __half* __restrict__ Y)
{
    extern __shared__ __half smh[];
    __half* Ks = smh;                 // [2][64][HST]
    __half* Vs = Ks + 2*FTILE;        // [2][64][HST]   (rows = d, cols = key)
    __half* Ps = Vs + 2*FTILE;        // [64][HST]      (Q staging, then P)

    const int tid  = threadIdx.x;
    const int lane = tid & 31;
    const int warp = tid >> 5;
    const int lr   = lane >> 2;
    const int lc   = lane & 3;
    const int qt   = blockIdx.x;
    const int bh   = blockIdx.y;
    const int r0   = warp*16 + lr;

    const __half* Qb = Q + (size_t)bh*SS*HDIM + (size_t)qt*64*HDIM;
    const __half* Kb = K + (size_t)bh*SS*HDIM;
    const __half* Vb = V + (size_t)bh*SS*HDIM;   // [d][key]

    // ---- stage Q (x0.125) into Ps as fp16, build persistent A-fragments ----
    const __half2 scale = __floats2half2_rn(0.125f, 0.125f);
    #pragma unroll
    for (int i = 0; i < 4; i++) {
        int idx = tid + i*128;
        int row = idx >> 3;
        int c8  = (idx & 7) << 3;
        uint4 raw = *(const uint4*)(Qb + row*HDIM + c8);
        __half2* h = (__half2*)&raw;
        h[0] = __hmul2(h[0], scale); h[1] = __hmul2(h[1], scale);
        h[2] = __hmul2(h[2], scale); h[3] = __hmul2(h[3], scale);
        *(uint4*)&Ps[row*HST + c8] = raw;
    }
    __syncthreads();

    uint32_t qf[4][4];
    #pragma unroll
    for (int ks = 0; ks < 4; ks++) {
        int kh = ks*16;
        qf[ks][0] = ldsm_u32(&Ps[ r0     *HST + kh + 2*lc    ]);
        qf[ks][1] = ldsm_u32(&Ps[(r0 + 8)*HST + kh + 2*lc    ]);
        qf[ks][2] = ldsm_u32(&Ps[ r0     *HST + kh + 2*lc + 8]);
        qf[ks][3] = ldsm_u32(&Ps[(r0 + 8)*HST + kh + 2*lc + 8]);
    }

    uint32_t smem_base = (uint32_t)__cvta_generic_to_shared(smh);

    auto load_kv = [&](int kt, int buf) {
        const __half* Kt = Kb + (size_t)kt*64*HDIM;
        const __half* Vt = Vb + (size_t)kt*64;       // column offset in [d][key]
        #pragma unroll
        for (int i = 0; i < 4; i++) {
            int idx = tid + i*128;
            int row = idx >> 3;           // key for K, d for V
            int c8  = (idx & 7) << 3;
            uint32_t dK = smem_base + (uint32_t)((buf*FTILE + row*HST + c8)*2);
            asm volatile("cp.async.cg.shared.global [%0], [%1], 16;"
                         :: "r"(dK), "l"(Kt + row*HDIM + c8));
            uint32_t dV = smem_base + (uint32_t)((2*FTILE + buf*FTILE + row*HST + c8)*2);
            asm volatile("cp.async.cg.shared.global [%0], [%1], 16;"
                         :: "r"(dV), "l"(Vt + (size_t)row*SS + c8));
        }
        asm volatile("cp.async.commit_group;");
    };

    load_kv(0, 0);

    float m0 = -1e30f, m1 = -1e30f, l0 = 0.f, l1 = 0.f;
    float o[8][4];
    #pragma unroll
    for (int ni = 0; ni < 8; ni++)
        #pragma unroll
        for (int r = 0; r < 4; r++) o[ni][r] = 0.f;

    for (int kt = 0; kt <= qt; kt++) {
        const int buf = kt & 1;
        asm volatile("cp.async.wait_group 0;");
        __syncthreads();
        if (kt < qt) load_kv(kt + 1, buf ^ 1);

        const __half* Kt = Ks + buf*FTILE;
        const __half* Vt = Vs + buf*FTILE;

        // ---- S = Qs @ K^T ----
        float s[8][4];
        #pragma unroll
        for (int ni = 0; ni < 8; ni++)
            #pragma unroll
            for (int r = 0; r < 4; r++) s[ni][r] = 0.f;

        #pragma unroll
        for (int ks = 0; ks < 4; ks++) {
            int kh = ks*16;
            #pragma unroll
            for (int ni = 0; ni < 8; ni++) {
                uint32_t b0 = ldsm_u32(&Kt[(ni*8 + lr)*HST + kh + 2*lc    ]);
                uint32_t b1 = ldsm_u32(&Kt[(ni*8 + lr)*HST + kh + 2*lc + 8]);
                MMA_F16(s[ni], qf[ks][0], qf[ks][1], qf[ks][2], qf[ks][3], b0, b1);
            }
        }

        // ---- causal mask on diagonal tile ----
        if (kt == qt) {
            #pragma unroll
            for (int ni = 0; ni < 8; ni++) {
                int c = ni*8 + 2*lc;
                if (c     > r0    ) s[ni][0] = -1e9f;
                if (c + 1 > r0    ) s[ni][1] = -1e9f;
                if (c     > r0 + 8) s[ni][2] = -1e9f;
                if (c + 1 > r0 + 8) s[ni][3] = -1e9f;
            }
        }

        // ---- online softmax ----
        float mx0 = -1e30f, mx1 = -1e30f;
        #pragma unroll
        for (int ni = 0; ni < 8; ni++) {
            mx0 = fmaxf(mx0, fmaxf(s[ni][0], s[ni][1]));
            mx1 = fmaxf(mx1, fmaxf(s[ni][2], s[ni][3]));
        }
        mx0 = fmaxf(mx0, __shfl_xor_sync(0xffffffffu, mx0, 1));
        mx0 = fmaxf(mx0, __shfl_xor_sync(0xffffffffu, mx0, 2));
        mx1 = fmaxf(mx1, __shfl_xor_sync(0xffffffffu, mx1, 1));
        mx1 = fmaxf(mx1, __shfl_xor_sync(0xffffffffu, mx1, 2));

        float mn0 = fmaxf(m0, mx0), mn1 = fmaxf(m1, mx1);
        float c0 = __expf(m0 - mn0), c1 = __expf(m1 - mn1);
        float rs0 = 0.f, rs1 = 0.f;
        #pragma unroll
        for (int ni = 0; ni < 8; ni++) {
            s[ni][0] = __expf(s[ni][0] - mn0);
            s[ni][1] = __expf(s[ni][1] - mn0);
            s[ni][2] = __expf(s[ni][2] - mn1);
            s[ni][3] = __expf(s[ni][3] - mn1);
            rs0 += s[ni][0] + s[ni][1];
            rs1 += s[ni][2] + s[ni][3];
        }
        rs0 += __shfl_xor_sync(0xffffffffu, rs0, 1);
        rs0 += __shfl_xor_sync(0xffffffffu, rs0, 2);
        rs1 += __shfl_xor_sync(0xffffffffu, rs1, 1);
        rs1 += __shfl_xor_sync(0xffffffffu, rs1, 2);
        l0 = l0*c0 + rs0;  m0 = mn0;
        l1 = l1*c1 + rs1;  m1 = mn1;

        #pragma unroll
        for (int ni = 0; ni < 8; ni++) {
            o[ni][0] *= c0;  o[ni][1] *= c0;
            o[ni][2] *= c1;  o[ni][3] *= c1;
            *(__half2*)&Ps[ r0     *HST + ni*8 + 2*lc] = __floats2half2_rn(s[ni][0], s[ni][1]);
            *(__half2*)&Ps[(r0 + 8)*HST + ni*8 + 2*lc] = __floats2half2_rn(s[ni][2], s[ni][3]);
        }
        __syncwarp();   // P rows are warp-private

        // ---- O += P @ V   (B = Vt[d][key], k = key contiguous) ----
        #pragma unroll
        for (int ks = 0; ks < 4; ks++) {
            int kh = ks*16;
            uint32_t a0 = ldsm_u32(&Ps[ r0     *HST + kh + 2*lc    ]);
            uint32_t a1 = ldsm_u32(&Ps[(r0 + 8)*HST + kh + 2*lc    ]);
            uint32_t a2 = ldsm_u32(&Ps[ r0     *HST + kh + 2*lc + 8]);
            uint32_t a3 = ldsm_u32(&Ps[(r0 + 8)*HST + kh + 2*lc + 8]);
            #pragma unroll
            for (int ni = 0; ni < 8; ni++) {
                uint32_t b0 = ldsm_u32(&Vt[(ni*8 + lr)*HST + kh + 2*lc    ]);
                uint32_t b1 = ldsm_u32(&Vt[(ni*8 + lr)*HST + kh + 2*lc + 8]);
                MMA_F16(o[ni], a0, a1, a2, a3, b0, b1);
            }
        }
    }

    // ---- normalize, store fp16 to [bh][q][d] ----
    float inv0 = 1.f / l0, inv1 = 1.f / l1;
    __half* Yb = Y + (size_t)bh*SS*HDIM + (size_t)qt*64*HDIM;
    #pragma unroll
    for (int ni = 0; ni < 8; ni++) {
        int c = ni*8 + 2*lc;
        *(__half2*)(Yb + (size_t) r0     *HDIM + c) = __floats2half2_rn(o[ni][0]*inv0, o[ni][1]*inv0);
        *(__half2*)(Yb + (size_t)(r0 + 8)*HDIM + c) = __floats2half2_rn(o[ni][2]*inv1, o[ni][3]*inv1);
    }
}

// ---------------------------------------------------------------------------
extern "C" void kernel_launch(void* const* d_in, const int* in_sizes, int n_in,
                              void* d_out, int out_size) {
    const float* q  = (const float*)d_in[0];
    const float* k  = (const float*)d_in[1];
    const float* v  = (const float*)d_in[2];
    // d_in[3] = mask (int32 tril) — causal structure implemented directly
    const float* bq = (const float*)d_in[5];
    const float* bk = (const float*)d_in[7];
    const float* bv = (const float*)d_in[9];
    const float* bo = (const float*)d_in[11];
    float* out = (float*)d_out;

    __half *q16, *k16, *v16, *wq16, *wk16, *wv16, *wo16, *qh16, *kh16, *vht16, *y16;
    cudaGetSymbolAddress((void**)&q16,  g_q16);
    cudaGetSymbolAddress((void**)&k16,  g_k16);
    cudaGetSymbolAddress((void**)&v16,  g_v16);
    cudaGetSymbolAddress((void**)&wq16, g_wq16);
    cudaGetSymbolAddress((void**)&wk16, g_wk16);
    cudaGetSymbolAddress((void**)&wv16, g_wv16);
    cudaGetSymbolAddress((void**)&wo16, g_wo16);
    cudaGetSymbolAddress((void**)&qh16, g_qh16);
    cudaGetSymbolAddress((void**)&kh16, g_kh16);
    cudaGetSymbolAddress((void**)&vht16, g_vht16);
    cudaGetSymbolAddress((void**)&y16,  g_y16);

    CvtArgs ca;
    ca.src[0] = q;                      ca.dst[0] = q16;  ca.n[0] = BB*SS*DD;
    ca.src[1] = k;                      ca.dst[1] = k16;  ca.n[1] = BB*SS*DD;
    ca.src[2] = v;                      ca.dst[2] = v16;  ca.n[2] = BB*SS*DD;
    ca.src[3] = (const float*)d_in[4];  ca.dst[3] = wq16; ca.n[3] = DD*DD;
    ca.src[4] = (const float*)d_in[6];  ca.dst[4] = wk16; ca.n[4] = DD*DD;
    ca.src[5] = (const float*)d_in[8];  ca.dst[5] = wv16; ca.n[5] = DD*DD;
    ca.src[6] = (const float*)d_in[10]; ca.dst[6] = wo16; ca.n[6] = DD*DD;
    convert_all<<<dim3(2048, 7), 256>>>(ca);

    const int gemm_smem = 4 * HTILE * (int)sizeof(__half);  // 73728 B
    cudaFuncSetAttribute(gemm_h<false,1>, cudaFuncAttributeMaxDynamicSharedMemorySize, gemm_smem);
    cudaFuncSetAttribute(gemm_h<false,2>, cudaFuncAttributeMaxDynamicSharedMemorySize, gemm_smem);
    cudaFuncSetAttribute(gemm_h<true,0>,  cudaFuncAttributeMaxDynamicSharedMemorySize, gemm_smem);

    dim3 ggrid(DD/128, (BB*SS)/128);   // (8, 32)
    gemm_h<false, 1><<<ggrid, 256, gemm_smem>>>(q16, wq16, bq, qh16,  BB*SS, DD, DD);
    gemm_h<false, 1><<<ggrid, 256, gemm_smem>>>(k16, wk16, bk, kh16,  BB*SS, DD, DD);
    gemm_h<false, 2><<<ggrid, 256, gemm_smem>>>(v16, wv16, bv, vht16, BB*SS, DD, DD);

    const int flash_smem = 5 * FTILE * (int)sizeof(__half);  // 46080 B
    cudaFuncSetAttribute(flash_attn_h, cudaFuncAttributeMaxDynamicSharedMemorySize, flash_smem);
    flash_attn_h<<<dim3(SS/64, NBH), 128, flash_smem>>>(qh16, kh16, vht16, y16);

    gemm_h<true, 0><<<ggrid, 256, gemm_smem>>>(y16, wo16, bo, out, BB*SS, DD, DD);
}

// round 6
// speedup vs baseline: 5.9670x; 1.0743x over previous
#include <cuda_runtime.h>
#include <cuda_fp16.h>
#include <cstdint>

#define BB 4
#define SS 1024
#define DD 1024
#define HH 16
#define HDIM 64
#define NBH (BB*HH)

// fp16 scratch (allocation-free)
__device__ __align__(16) __half g_q16 [BB*SS*DD];
__device__ __align__(16) __half g_k16 [BB*SS*DD];
__device__ __align__(16) __half g_v16 [BB*SS*DD];
__device__ __align__(16) __half g_wq16[DD*DD];
__device__ __align__(16) __half g_wk16[DD*DD];
__device__ __align__(16) __half g_wv16[DD*DD];
__device__ __align__(16) __half g_wo16[DD*DD];
__device__ __align__(16) __half g_qh16[NBH*SS*HDIM];   // [bh][q][d]
__device__ __align__(16) __half g_kh16[NBH*SS*HDIM];   // [bh][key][d]
__device__ __align__(16) __half g_vht16[NBH*SS*HDIM];  // [bh][d][key]  TRANSPOSED
__device__ __align__(16) __half g_y16 [NBH*SS*HDIM];   // [bh][q][d]

#define MMA_F16(acc, a0,a1,a2,a3, b0,b1)                                    \
    asm volatile(                                                           \
        "mma.sync.aligned.m16n8k16.row.col.f32.f16.f16.f32 "                \
        "{%0,%1,%2,%3}, {%4,%5,%6,%7}, {%8,%9}, {%0,%1,%2,%3};"             \
        : "+f"(acc[0]), "+f"(acc[1]), "+f"(acc[2]), "+f"(acc[3])            \
        : "r"(a0), "r"(a1), "r"(a2), "r"(a3), "r"(b0), "r"(b1))

__device__ __forceinline__ void ldmx4(uint32_t& r0, uint32_t& r1,
                                      uint32_t& r2, uint32_t& r3, uint32_t addr) {
    asm volatile("ldmatrix.sync.aligned.m8n8.x4.shared.b16 {%0,%1,%2,%3}, [%4];"
                 : "=r"(r0), "=r"(r1), "=r"(r2), "=r"(r3) : "r"(addr));
}

// ---------------------------------------------------------------------------
// Fused fp32 -> fp16 conversion for 7 tensors in one launch.
// ---------------------------------------------------------------------------
struct CvtArgs {
    const float* src[7];
    __half*      dst[7];
    int          n[7];
};

__global__ void __launch_bounds__(256) convert_all(CvtArgs args) {
    const int t = blockIdx.y;
    const int n = args.n[t];
    int base = (blockIdx.x * 256 + threadIdx.x) * 8;
    if (base >= n) return;
    const float4* s = (const float4*)(args.src[t] + base);
    float4 f0 = s[0], f1 = s[1];
    __half2 h0 = __floats2half2_rn(f0.x, f0.y);
    __half2 h1 = __floats2half2_rn(f0.z, f0.w);
    __half2 h2 = __floats2half2_rn(f1.x, f1.y);
    __half2 h3 = __floats2half2_rn(f1.z, f1.w);
    uint4 o;
    o.x = *(uint32_t*)&h0; o.y = *(uint32_t*)&h1;
    o.z = *(uint32_t*)&h2; o.w = *(uint32_t*)&h3;
    *(uint4*)(args.dst[t] + base) = o;
}

// ---------------------------------------------------------------------------
// FP16 tensor-core GEMM + bias + ReLU (round-4 design + ldmatrix fragments).
// C[m][n] = relu(sum_k A[m][k]*W[n][k] + bias[n])
// BM=BN=128, BK=64, 256 threads (8 warps 4x2), warp tile 32x64, m16n8k16.
// OUT_MODE: 0 = fp32 row-major, 1 = fp16 split-head [bh][s][d],
//           2 = fp16 split-head transposed [bh][d][s]
// smem stride 72 halves: ldmatrix row skew 36 words -> conflict-free.
// ---------------------------------------------------------------------------
#define GBK 64
#define HST 72
#define HTILE (128*HST)   // halves per buffer per matrix

template<bool IN_SPLIT, int OUT_MODE>
__global__ void __launch_bounds__(256, 2) gemm_h(
    const __half* __restrict__ A, const __half* __restrict__ W,
    const float* __restrict__ bias, void* __restrict__ Cv,
    int M, int N, int K)
{
    extern __shared__ __half smh[];
    __half* As = smh;              // [2][128][HST]
    __half* Ws = smh + 2*HTILE;    // [2][128][HST]

    const int tid  = threadIdx.x;
    const int lane = tid & 31;
    const int warp = tid >> 5;
    const int wm   = warp & 3;
    const int wn   = warp >> 2;
    const int lr   = lane >> 2;
    const int lc   = lane & 3;
    const int bm   = blockIdx.y * 128;
    const int bn   = blockIdx.x * 128;

    float acc[2][8][4];
    #pragma unroll
    for (int mi = 0; mi < 2; mi++)
        #pragma unroll
        for (int ni = 0; ni < 8; ni++)
            #pragma unroll
            for (int r = 0; r < 4; r++) acc[mi][ni][r] = 0.f;

    uint32_t smem_base = (uint32_t)__cvta_generic_to_shared(smh);
    const int nt = K / GBK;

    // per-lane ldmatrix offsets (halves)
    const int aRow = wm*32 + (lane & 15);
    const int aCol = (lane >> 4) << 3;
    const int bRow = wn*64 + (lane & 7) + ((lane & 16) >> 1);
    const int bCol = (lane & 8);

    auto load_tile = [&](int k0, int buf) {
        #pragma unroll
        for (int i = 0; i < 4; i++) {
            int idx  = i*256 + tid;
            int row  = idx >> 3;           // 0..127
            int kc   = (idx & 7) << 3;     // halves 0,8,...,56
            const __half* srcA;
            if (IN_SPLIT) {
                int gm = bm + row, gk = k0 + kc;
                srcA = A + ((size_t)((gm >> 10)*HH + (gk >> 6)))*(SS*HDIM)
                         + (size_t)(gm & 1023)*HDIM + (gk & 63);
            } else {
                srcA = A + (size_t)(bm + row)*K + k0 + kc;
            }
            uint32_t dA = smem_base + (uint32_t)((buf*HTILE + row*HST + kc) * 2);
            asm volatile("cp.async.cg.shared.global [%0], [%1], 16;" :: "r"(dA), "l"(srcA));

            const __half* srcW = W + (size_t)(bn + row)*K + k0 + kc;
            uint32_t dW = smem_base + (uint32_t)((2*HTILE + buf*HTILE + row*HST + kc) * 2);
            asm volatile("cp.async.cg.shared.global [%0], [%1], 16;" :: "r"(dW), "l"(srcW));
        }
        asm volatile("cp.async.commit_group;");
    };

    load_tile(0, 0);

    for (int kt = 0; kt < nt; kt++) {
        asm volatile("cp.async.wait_group 0;");
        __syncthreads();
        if (kt + 1 < nt) load_tile((kt+1)*GBK, (kt+1) & 1);

        const uint32_t abuf = smem_base + (uint32_t)(((kt & 1)*HTILE) * 2);
        const uint32_t bbuf = smem_base + (uint32_t)(((2 + (kt & 1))*HTILE) * 2);

        #pragma unroll
        for (int ks = 0; ks < 4; ks++) {
            const int kh = ks*16;          // halves
            uint32_t a[2][4], b[8][2];
            #pragma unroll
            for (int mi = 0; mi < 2; mi++)
                ldmx4(a[mi][0], a[mi][1], a[mi][2], a[mi][3],
                      abuf + (uint32_t)(((aRow + mi*16)*HST + kh + aCol) * 2));
            #pragma unroll
            for (int np = 0; np < 4; np++)
                ldmx4(b[2*np][0], b[2*np][1], b[2*np+1][0], b[2*np+1][1],
                      bbuf + (uint32_t)(((bRow + np*16)*HST + kh + bCol) * 2));
            #pragma unroll
            for (int mi = 0; mi < 2; mi++)
                #pragma unroll
                for (int ni = 0; ni < 8; ni++)
                    MMA_F16(acc[mi][ni],
                            a[mi][0], a[mi][1], a[mi][2], a[mi][3],
                            b[ni][0], b[ni][1]);
        }
        __syncthreads();
    }

    #pragma unroll
    for (int mi = 0; mi < 2; mi++) {
        #pragma unroll
        for (int ni = 0; ni < 8; ni++) {
            int m = bm + wm*32 + mi*16 + lr;
            int n = bn + wn*64 + ni*8 + 2*lc;
            float2 bv = *(const float2*)(bias + n);
            float v00 = fmaxf(acc[mi][ni][0] + bv.x, 0.f);
            float v01 = fmaxf(acc[mi][ni][1] + bv.y, 0.f);
            float v10 = fmaxf(acc[mi][ni][2] + bv.x, 0.f);
            float v11 = fmaxf(acc[mi][ni][3] + bv.y, 0.f);
            if (OUT_MODE == 0) {
                float* C = (float*)Cv;
                float2 r0; r0.x = v00; r0.y = v01;
                float2 r1; r1.x = v10; r1.y = v11;
                *(float2*)(C + (size_t)m*N + n)     = r0;
                *(float2*)(C + (size_t)(m+8)*N + n) = r1;
            } else if (OUT_MODE == 1) {
                __half* C = (__half*)Cv;
                size_t head = (size_t)((m >> 10)*HH + (n >> 6))*(SS*HDIM) + (n & 63);
                *(__half2*)(C + head + (size_t)( m    & 1023)*HDIM) = __floats2half2_rn(v00, v01);
                *(__half2*)(C + head + (size_t)((m+8) & 1023)*HDIM) = __floats2half2_rn(v10, v11);
            } else {
                __half* C = (__half*)Cv;   // [bh][d][s]
                size_t head = (size_t)((m >> 10)*HH + (n >> 6))*(SS*HDIM);
                size_t drow0 = head + (size_t)(n & 63)*SS;
                size_t drow1 = head + (size_t)((n+1) & 63)*SS;
                C[drow0 + ( m    & 1023)] = __float2half_rn(v00);
                C[drow1 + ( m    & 1023)] = __float2half_rn(v01);
                C[drow0 + ((m+8) & 1023)] = __float2half_rn(v10);
                C[drow1 + ((m+8) & 1023)] = __float2half_rn(v11);
            }
        }
    }
}

// ---------------------------------------------------------------------------
// Causal flash attention, fp16 mma + ldmatrix fragments.
// 1 block = (64-query tile, bh). 128 threads / 4 warps; warp owns 16 q rows.
// ---------------------------------------------------------------------------
#define FTILE (64*HST)

__global__ void __launch_bounds__(128, 3) flash_attn_h(
    const __half* __restrict__ Q, const __half* __restrict__ K,
    const __half* __restrict__ V, __half* __restrict__ Y)
{
    extern __shared__ __half smh[];
    __half* Ks = smh;                 // [2][64][HST]
    __half* Vs = Ks + 2*FTILE;        // [2][64][HST]   (rows = d, cols = key)
    __half* Ps = Vs + 2*FTILE;        // [64][HST]      (Q staging, then P)

    const int tid  = threadIdx.x;
    const int lane = tid & 31;
    const int warp = tid >> 5;
    const int lr   = lane >> 2;
    const int lc   = lane & 3;
    const int qt   = blockIdx.x;
    const int bh   = blockIdx.y;
    const int r0   = warp*16 + lr;

    const __half* Qb = Q + (size_t)bh*SS*HDIM + (size_t)qt*64*HDIM;
    const __half* Kb = K + (size_t)bh*SS*HDIM;
    const __half* Vb = V + (size_t)bh*SS*HDIM;   // [d][key]

    uint32_t smem_base = (uint32_t)__cvta_generic_to_shared(smh);
    const uint32_t psbase = smem_base + (uint32_t)(4*FTILE*2);

    // per-lane ldmatrix offsets (halves)
    const int aRow = warp*16 + (lane & 15);          // A-operand rows (Q, P)
    const int aCol = (lane >> 4) << 3;
    const int bRow = (lane & 7) + ((lane & 16) >> 1); // B-operand rows (K, V)
    const int bCol = (lane & 8);

    // ---- stage Q (x0.125) into Ps as fp16, build persistent A-fragments ----
    const __half2 scale = __floats2half2_rn(0.125f, 0.125f);
    #pragma unroll
    for (int i = 0; i < 4; i++) {
        int idx = tid + i*128;
        int row = idx >> 3;
        int c8  = (idx & 7) << 3;
        uint4 raw = *(const uint4*)(Qb + row*HDIM + c8);
        __half2* h = (__half2*)&raw;
        h[0] = __hmul2(h[0], scale); h[1] = __hmul2(h[1], scale);
        h[2] = __hmul2(h[2], scale); h[3] = __hmul2(h[3], scale);
        *(uint4*)&Ps[row*HST + c8] = raw;
    }
    __syncthreads();

    uint32_t qf[4][4];
    #pragma unroll
    for (int ks = 0; ks < 4; ks++)
        ldmx4(qf[ks][0], qf[ks][1], qf[ks][2], qf[ks][3],
              psbase + (uint32_t)((aRow*HST + ks*16 + aCol) * 2));

    auto load_kv = [&](int kt, int buf) {
        const __half* Kt = Kb + (size_t)kt*64*HDIM;
        const __half* Vt = Vb + (size_t)kt*64;
        #pragma unroll
        for (int i = 0; i < 4; i++) {
            int idx = tid + i*128;
            int row = idx >> 3;
            int c8  = (idx & 7) << 3;
            uint32_t dK = smem_base + (uint32_t)((buf*FTILE + row*HST + c8)*2);
            asm volatile("cp.async.cg.shared.global [%0], [%1], 16;"
                         :: "r"(dK), "l"(Kt + row*HDIM + c8));
            uint32_t dV = smem_base + (uint32_t)((2*FTILE + buf*FTILE + row*HST + c8)*2);
            asm volatile("cp.async.cg.shared.global [%0], [%1], 16;"
                         :: "r"(dV), "l"(Vt + (size_t)row*SS + c8));
        }
        asm volatile("cp.async.commit_group;");
    };

    load_kv(0, 0);

    float m0 = -1e30f, m1 = -1e30f, l0 = 0.f, l1 = 0.f;
    float o[8][4];
    #pragma unroll
    for (int ni = 0; ni < 8; ni++)
        #pragma unroll
        for (int r = 0; r < 4; r++) o[ni][r] = 0.f;

    for (int kt = 0; kt <= qt; kt++) {
        const int buf = kt & 1;
        asm volatile("cp.async.wait_group 0;");
        __syncthreads();
        if (kt < qt) load_kv(kt + 1, buf ^ 1);

        const uint32_t kbuf = smem_base + (uint32_t)((buf*FTILE)*2);
        const uint32_t vbuf = smem_base + (uint32_t)(((2 + buf)*FTILE)*2);

        // ---- S = Qs @ K^T ----
        float s[8][4];
        #pragma unroll
        for (int ni = 0; ni < 8; ni++)
            #pragma unroll
            for (int r = 0; r < 4; r++) s[ni][r] = 0.f;

        #pragma unroll
        for (int ks = 0; ks < 4; ks++) {
            int kh = ks*16;
            uint32_t b[8][2];
            #pragma unroll
            for (int np = 0; np < 4; np++)
                ldmx4(b[2*np][0], b[2*np][1], b[2*np+1][0], b[2*np+1][1],
                      kbuf + (uint32_t)(((bRow + np*16)*HST + kh + bCol) * 2));
            #pragma unroll
            for (int ni = 0; ni < 8; ni++)
                MMA_F16(s[ni], qf[ks][0], qf[ks][1], qf[ks][2], qf[ks][3],
                        b[ni][0], b[ni][1]);
        }

        // ---- causal mask on diagonal tile ----
        if (kt == qt) {
            #pragma unroll
            for (int ni = 0; ni < 8; ni++) {
                int c = ni*8 + 2*lc;
                if (c     > r0    ) s[ni][0] = -1e9f;
                if (c + 1 > r0    ) s[ni][1] = -1e9f;
                if (c     > r0 + 8) s[ni][2] = -1e9f;
                if (c + 1 > r0 + 8) s[ni][3] = -1e9f;
            }
        }

        // ---- online softmax ----
        float mx0 = -1e30f, mx1 = -1e30f;
        #pragma unroll
        for (int ni = 0; ni < 8; ni++) {
            mx0 = fmaxf(mx0, fmaxf(s[ni][0], s[ni][1]));
            mx1 = fmaxf(mx1, fmaxf(s[ni][2], s[ni][3]));
        }
        mx0 = fmaxf(mx0, __shfl_xor_sync(0xffffffffu, mx0, 1));
        mx0 = fmaxf(mx0, __shfl_xor_sync(0xffffffffu, mx0, 2));
        mx1 = fmaxf(mx1, __shfl_xor_sync(0xffffffffu, mx1, 1));
        mx1 = fmaxf(mx1, __shfl_xor_sync(0xffffffffu, mx1, 2));

        float mn0 = fmaxf(m0, mx0), mn1 = fmaxf(m1, mx1);
        float c0 = __expf(m0 - mn0), c1 = __expf(m1 - mn1);
        float rs0 = 0.f, rs1 = 0.f;
        #pragma unroll
        for (int ni = 0; ni < 8; ni++) {
            s[ni][0] = __expf(s[ni][0] - mn0);
            s[ni][1] = __expf(s[ni][1] - mn0);
            s[ni][2] = __expf(s[ni][2] - mn1);
            s[ni][3] = __expf(s[ni][3] - mn1);
            rs0 += s[ni][0] + s[ni][1];
            rs1 += s[ni][2] + s[ni][3];
        }
        rs0 += __shfl_xor_sync(0xffffffffu, rs0, 1);
        rs0 += __shfl_xor_sync(0xffffffffu, rs0, 2);
        rs1 += __shfl_xor_sync(0xffffffffu, rs1, 1);
        rs1 += __shfl_xor_sync(0xffffffffu, rs1, 2);
        l0 = l0*c0 + rs0;  m0 = mn0;
        l1 = l1*c1 + rs1;  m1 = mn1;

        #pragma unroll
        for (int ni = 0; ni < 8; ni++) {
            o[ni][0] *= c0;  o[ni][1] *= c0;
            o[ni][2] *= c1;  o[ni][3] *= c1;
            *(__half2*)&Ps[ r0     *HST + ni*8 + 2*lc] = __floats2half2_rn(s[ni][0], s[ni][1]);
            *(__half2*)&Ps[(r0 + 8)*HST + ni*8 + 2*lc] = __floats2half2_rn(s[ni][2], s[ni][3]);
        }
        __syncwarp();   // P rows are warp-private

        // ---- O += P @ V ----
        #pragma unroll
        for (int ks = 0; ks < 4; ks++) {
            int kh = ks*16;
            uint32_t a0, a1, a2, a3;
            ldmx4(a0, a1, a2, a3, psbase + (uint32_t)((aRow*HST + kh + aCol) * 2));
            uint32_t b[8][2];
            #pragma unroll
            for (int np = 0; np < 4; np++)
                ldmx4(b[2*np][0], b[2*np][1], b[2*np+1][0], b[2*np+1][1],
                      vbuf + (uint32_t)(((bRow + np*16)*HST + kh + bCol) * 2));
            #pragma unroll
            for (int ni = 0; ni < 8; ni++)
                MMA_F16(o[ni], a0, a1, a2, a3, b[ni][0], b[ni][1]);
        }
    }

    // ---- normalize, store fp16 to [bh][q][d] ----
    float inv0 = 1.f / l0, inv1 = 1.f / l1;
    __half* Yb = Y + (size_t)bh*SS*HDIM + (size_t)qt*64*HDIM;
    #pragma unroll
    for (int ni = 0; ni < 8; ni++) {
        int c = ni*8 + 2*lc;
        *(__half2*)(Yb + (size_t) r0     *HDIM + c) = __floats2half2_rn(o[ni][0]*inv0, o[ni][1]*inv0);
        *(__half2*)(Yb + (size_t)(r0 + 8)*HDIM + c) = __floats2half2_rn(o[ni][2]*inv1, o[ni][3]*inv1);
    }
}

// ---------------------------------------------------------------------------
extern "C" void kernel_launch(void* const* d_in, const int* in_sizes, int n_in,
                              void* d_out, int out_size) {
    const float* q  = (const float*)d_in[0];
    const float* k  = (const float*)d_in[1];
    const float* v  = (const float*)d_in[2];
    // d_in[3] = mask (int32 tril) — causal structure implemented directly
    const float* bq = (const float*)d_in[5];
    const float* bk = (const float*)d_in[7];
    const float* bv = (const float*)d_in[9];
    const float* bo = (const float*)d_in[11];
    float* out = (float*)d_out;

    __half *q16, *k16, *v16, *wq16, *wk16, *wv16, *wo16, *qh16, *kh16, *vht16, *y16;
    cudaGetSymbolAddress((void**)&q16,  g_q16);
    cudaGetSymbolAddress((void**)&k16,  g_k16);
    cudaGetSymbolAddress((void**)&v16,  g_v16);
    cudaGetSymbolAddress((void**)&wq16, g_wq16);
    cudaGetSymbolAddress((void**)&wk16, g_wk16);
    cudaGetSymbolAddress((void**)&wv16, g_wv16);
    cudaGetSymbolAddress((void**)&wo16, g_wo16);
    cudaGetSymbolAddress((void**)&qh16, g_qh16);
    cudaGetSymbolAddress((void**)&kh16, g_kh16);
    cudaGetSymbolAddress((void**)&vht16, g_vht16);
    cudaGetSymbolAddress((void**)&y16,  g_y16);

    CvtArgs ca;
    ca.src[0] = q;                      ca.dst[0] = q16;  ca.n[0] = BB*SS*DD;
    ca.src[1] = k;                      ca.dst[1] = k16;  ca.n[1] = BB*SS*DD;
    ca.src[2] = v;                      ca.dst[2] = v16;  ca.n[2] = BB*SS*DD;
    ca.src[3] = (const float*)d_in[4];  ca.dst[3] = wq16; ca.n[3] = DD*DD;
    ca.src[4] = (const float*)d_in[6];  ca.dst[4] = wk16; ca.n[4] = DD*DD;
    ca.src[5] = (const float*)d_in[8];  ca.dst[5] = wv16; ca.n[5] = DD*DD;
    ca.src[6] = (const float*)d_in[10]; ca.dst[6] = wo16; ca.n[6] = DD*DD;
    convert_all<<<dim3(2048, 7), 256>>>(ca);

    const int gemm_smem = 4 * HTILE * (int)sizeof(__half);  // 73728 B
    cudaFuncSetAttribute(gemm_h<false,1>, cudaFuncAttributeMaxDynamicSharedMemorySize, gemm_smem);
    cudaFuncSetAttribute(gemm_h<false,2>, cudaFuncAttributeMaxDynamicSharedMemorySize, gemm_smem);
    cudaFuncSetAttribute(gemm_h<true,0>,  cudaFuncAttributeMaxDynamicSharedMemorySize, gemm_smem);

    dim3 ggrid(DD/128, (BB*SS)/128);   // (8, 32)
    gemm_h<false, 1><<<ggrid, 256, gemm_smem>>>(q16, wq16, bq, qh16,  BB*SS, DD, DD);
    gemm_h<false, 1><<<ggrid, 256, gemm_smem>>>(k16, wk16, bk, kh16,  BB*SS, DD, DD);
    gemm_h<false, 2><<<ggrid, 256, gemm_smem>>>(v16, wv16, bv, vht16, BB*SS, DD, DD);

    const int flash_smem = 5 * FTILE * (int)sizeof(__half);  // 46080 B
    cudaFuncSetAttribute(flash_attn_h, cudaFuncAttributeMaxDynamicSharedMemorySize, flash_smem);
    flash_attn_h<<<dim3(SS/64, NBH), 128, flash_smem>>>(qh16, kh16, vht16, y16);

    gemm_h<true, 0><<<ggrid, 256, gemm_smem>>>(y16, wo16, bo, out, BB*SS, DD, DD);
}

// round 7
// speedup vs baseline: 6.1057x; 1.0232x over previous
#include <cuda_runtime.h>
#include <cuda_fp16.h>
#include <cstdint>

#define BB 4
#define SS 1024
#define DD 1024
#define HH 16
#define HDIM 64
#define NBH (BB*HH)

// fp16 scratch (allocation-free)
__device__ __align__(16) __half g_q16 [BB*SS*DD];
__device__ __align__(16) __half g_k16 [BB*SS*DD];
__device__ __align__(16) __half g_v16 [BB*SS*DD];
__device__ __align__(16) __half g_wq16[DD*DD];
__device__ __align__(16) __half g_wk16[DD*DD];
__device__ __align__(16) __half g_wv16[DD*DD];
__device__ __align__(16) __half g_wo16[DD*DD];
__device__ __align__(16) __half g_qh16[NBH*SS*HDIM];   // [bh][q][d]
__device__ __align__(16) __half g_kh16[NBH*SS*HDIM];   // [bh][key][d]
__device__ __align__(16) __half g_vht16[NBH*SS*HDIM];  // [bh][d][key]  TRANSPOSED
__device__ __align__(16) __half g_y16 [NBH*SS*HDIM];   // [bh][q][d]

#define MMA_F16(acc, a0,a1,a2,a3, b0,b1)                                    \
    asm volatile(                                                           \
        "mma.sync.aligned.m16n8k16.row.col.f32.f16.f16.f32 "                \
        "{%0,%1,%2,%3}, {%4,%5,%6,%7}, {%8,%9}, {%0,%1,%2,%3};"             \
        : "+f"(acc[0]), "+f"(acc[1]), "+f"(acc[2]), "+f"(acc[3])            \
        : "r"(a0), "r"(a1), "r"(a2), "r"(a3), "r"(b0), "r"(b1))

__device__ __forceinline__ void ldmx4(uint32_t& r0, uint32_t& r1,
                                      uint32_t& r2, uint32_t& r3, uint32_t addr) {
    asm volatile("ldmatrix.sync.aligned.m8n8.x4.shared.b16 {%0,%1,%2,%3}, [%4];"
                 : "=r"(r0), "=r"(r1), "=r"(r2), "=r"(r3) : "r"(addr));
}

// ---------------------------------------------------------------------------
// Fused fp32 -> fp16 conversion for 7 tensors in one launch.
// ---------------------------------------------------------------------------
struct CvtArgs {
    const float* src[7];
    __half*      dst[7];
    int          n[7];
};

__global__ void __launch_bounds__(256) convert_all(CvtArgs args) {
    const int t = blockIdx.y;
    const int n = args.n[t];
    int base = (blockIdx.x * 256 + threadIdx.x) * 8;
    if (base >= n) return;
    const float4* s = (const float4*)(args.src[t] + base);
    float4 f0 = s[0], f1 = s[1];
    __half2 h0 = __floats2half2_rn(f0.x, f0.y);
    __half2 h1 = __floats2half2_rn(f0.z, f0.w);
    __half2 h2 = __floats2half2_rn(f1.x, f1.y);
    __half2 h3 = __floats2half2_rn(f1.z, f1.w);
    uint4 o;
    o.x = *(uint32_t*)&h0; o.y = *(uint32_t*)&h1;
    o.z = *(uint32_t*)&h2; o.w = *(uint32_t*)&h3;
    *(uint4*)(args.dst[t] + base) = o;
}

// ---------------------------------------------------------------------------
// FP16 tensor-core GEMM + bias + ReLU, 3-stage cp.async pipeline.
// C[m][n] = relu(sum_k A[m][k]*W[n][k] + bias[n])
// BM=BN=128, BK=64, 256 threads (8 warps 4x2), warp tile 32x64, m16n8k16.
// Stage layout: [stage][A(128x72) | W(128x72)] halves, 3 stages (110592 B).
// wait_group 1 keeps 2 chunks in flight while computing.
// ---------------------------------------------------------------------------
#define GBK 64
#define HST 72
#define HTILE (128*HST)                 // halves per matrix per stage
#define STAGEH (2*HTILE)                // halves per stage (A+W)
#define GEMM_SMEM (3*STAGEH*2)          // 110592 bytes

struct QKVArgs {
    const __half* A[3];
    const __half* W[3];
    const float*  b[3];
    __half*       C[3];
};

// shared inner machinery --------------------------------------------------
struct GemmCore {
    uint32_t smem_base;
    int tid, lane, warp, wm, wn, lr, lc, bm, bn;
    int aRow, aCol, bRow, bCol;

    __device__ __forceinline__ void init(uint32_t sb) {
        smem_base = sb;
        tid  = threadIdx.x;
        lane = tid & 31;
        warp = tid >> 5;
        wm   = warp & 3;
        wn   = warp >> 2;
        lr   = lane >> 2;
        lc   = lane & 3;
        bm   = blockIdx.y * 128;
        bn   = blockIdx.x * 128;
        aRow = wm*32 + (lane & 15);
        aCol = (lane >> 4) << 3;
        bRow = wn*64 + (lane & 7) + ((lane & 16) >> 1);
        bCol = (lane & 8);
    }

    template<bool IN_SPLIT>
    __device__ __forceinline__ void load_tile(const __half* A, const __half* W,
                                              int K, int k0, int st) {
        const uint32_t abase = smem_base + (uint32_t)(st*STAGEH*2);
        const uint32_t wbase = abase + (uint32_t)(HTILE*2);
        #pragma unroll
        for (int i = 0; i < 4; i++) {
            int idx  = i*256 + tid;
            int row  = idx >> 3;
            int kc   = (idx & 7) << 3;
            const __half* srcA;
            if (IN_SPLIT) {
                int gm = bm + row, gk = k0 + kc;
                srcA = A + ((size_t)((gm >> 10)*HH + (gk >> 6)))*(SS*HDIM)
                         + (size_t)(gm & 1023)*HDIM + (gk & 63);
            } else {
                srcA = A + (size_t)(bm + row)*K + k0 + kc;
            }
            uint32_t dA = abase + (uint32_t)((row*HST + kc) * 2);
            asm volatile("cp.async.cg.shared.global [%0], [%1], 16;" :: "r"(dA), "l"(srcA));
            const __half* srcW = W + (size_t)(bn + row)*K + k0 + kc;
            uint32_t dW = wbase + (uint32_t)((row*HST + kc) * 2);
            asm volatile("cp.async.cg.shared.global [%0], [%1], 16;" :: "r"(dW), "l"(srcW));
        }
        asm volatile("cp.async.commit_group;");
    }

    __device__ __forceinline__ void compute(int st, float acc[2][8][4]) {
        const uint32_t abuf = smem_base + (uint32_t)(st*STAGEH*2);
        const uint32_t bbuf = abuf + (uint32_t)(HTILE*2);
        #pragma unroll
        for (int ks = 0; ks < 4; ks++) {
            const int kh = ks*16;
            uint32_t a[2][4], b[8][2];
            #pragma unroll
            for (int mi = 0; mi < 2; mi++)
                ldmx4(a[mi][0], a[mi][1], a[mi][2], a[mi][3],
                      abuf + (uint32_t)(((aRow + mi*16)*HST + kh + aCol) * 2));
            #pragma unroll
            for (int np = 0; np < 4; np++)
                ldmx4(b[2*np][0], b[2*np][1], b[2*np+1][0], b[2*np+1][1],
                      bbuf + (uint32_t)(((bRow + np*16)*HST + kh + bCol) * 2));
            #pragma unroll
            for (int mi = 0; mi < 2; mi++)
                #pragma unroll
                for (int ni = 0; ni < 8; ni++)
                    MMA_F16(acc[mi][ni],
                            a[mi][0], a[mi][1], a[mi][2], a[mi][3],
                            b[ni][0], b[ni][1]);
        }
    }
};

template<bool IN_SPLIT>
__device__ __forceinline__ void gemm_mainloop(GemmCore& g, const __half* A,
                                              const __half* W, int K,
                                              float acc[2][8][4]) {
    const int nt = K / GBK;   // 16
    g.load_tile<IN_SPLIT>(A, W, K, 0, 0);
    g.load_tile<IN_SPLIT>(A, W, K, GBK, 1);
    #pragma unroll 1
    for (int kt = 0; kt < nt; kt++) {
        if (kt < nt - 1) asm volatile("cp.async.wait_group 1;" ::: "memory");
        else             asm volatile("cp.async.wait_group 0;" ::: "memory");
        __syncthreads();
        if (kt + 2 < nt) {
            int st = kt + 2; st -= (st >= 3) ? 3 : 0; st -= (st >= 3) ? 3 : 0;
            // (kt+2) % 3 for kt in [0,13]: compute cheaply
            g.load_tile<IN_SPLIT>(A, W, K, (kt+2)*GBK, (kt+2) % 3);
        }
        g.compute(kt % 3, acc);
    }
}

// epilogue helpers ----------------------------------------------------------
__device__ __forceinline__ void epi_mode1(GemmCore& g, float acc[2][8][4],
                                          const float* bias, __half* C) {
    #pragma unroll
    for (int mi = 0; mi < 2; mi++)
        #pragma unroll
        for (int ni = 0; ni < 8; ni++) {
            int m = g.bm + g.wm*32 + mi*16 + g.lr;
            int n = g.bn + g.wn*64 + ni*8 + 2*g.lc;
            float2 bv = *(const float2*)(bias + n);
            float v00 = fmaxf(acc[mi][ni][0] + bv.x, 0.f);
            float v01 = fmaxf(acc[mi][ni][1] + bv.y, 0.f);
            float v10 = fmaxf(acc[mi][ni][2] + bv.x, 0.f);
            float v11 = fmaxf(acc[mi][ni][3] + bv.y, 0.f);
            size_t head = (size_t)((m >> 10)*HH + (n >> 6))*(SS*HDIM) + (n & 63);
            *(__half2*)(C + head + (size_t)( m    & 1023)*HDIM) = __floats2half2_rn(v00, v01);
            *(__half2*)(C + head + (size_t)((m+8) & 1023)*HDIM) = __floats2half2_rn(v10, v11);
        }
}

__device__ __forceinline__ void epi_mode2(GemmCore& g, float acc[2][8][4],
                                          const float* bias, __half* C) {
    #pragma unroll
    for (int mi = 0; mi < 2; mi++)
        #pragma unroll
        for (int ni = 0; ni < 8; ni++) {
            int m = g.bm + g.wm*32 + mi*16 + g.lr;
            int n = g.bn + g.wn*64 + ni*8 + 2*g.lc;
            float2 bv = *(const float2*)(bias + n);
            float v00 = fmaxf(acc[mi][ni][0] + bv.x, 0.f);
            float v01 = fmaxf(acc[mi][ni][1] + bv.y, 0.f);
            float v10 = fmaxf(acc[mi][ni][2] + bv.x, 0.f);
            float v11 = fmaxf(acc[mi][ni][3] + bv.y, 0.f);
            size_t head = (size_t)((m >> 10)*HH + (n >> 6))*(SS*HDIM);
            size_t drow0 = head + (size_t)(n & 63)*SS;
            size_t drow1 = head + (size_t)((n+1) & 63)*SS;
            C[drow0 + ( m    & 1023)] = __float2half_rn(v00);
            C[drow1 + ( m    & 1023)] = __float2half_rn(v01);
            C[drow0 + ((m+8) & 1023)] = __float2half_rn(v10);
            C[drow1 + ((m+8) & 1023)] = __float2half_rn(v11);
        }
}

// fused Q/K/V projection: blockIdx.z selects tensor; z==2 (V) stores transposed
__global__ void __launch_bounds__(256, 2) gemm_qkv(QKVArgs args) {
    extern __shared__ __half smh[];
    GemmCore g; g.init((uint32_t)__cvta_generic_to_shared(smh));
    const int z = blockIdx.z;
    const __half* A = args.A[z];
    const __half* W = args.W[z];

    float acc[2][8][4];
    #pragma unroll
    for (int mi = 0; mi < 2; mi++)
        #pragma unroll
        for (int ni = 0; ni < 8; ni++)
            #pragma unroll
            for (int r = 0; r < 4; r++) acc[mi][ni][r] = 0.f;

    gemm_mainloop<false>(g, A, W, DD, acc);

    if (z == 2) epi_mode2(g, acc, args.b[z], args.C[z]);
    else        epi_mode1(g, acc, args.b[z], args.C[z]);
}

// output projection: split-head fp16 in, fp32 row-major out
__global__ void __launch_bounds__(256, 2) gemm_out(
    const __half* __restrict__ A, const __half* __restrict__ W,
    const float* __restrict__ bias, float* __restrict__ C)
{
    extern __shared__ __half smh[];
    GemmCore g; g.init((uint32_t)__cvta_generic_to_shared(smh));

    float acc[2][8][4];
    #pragma unroll
    for (int mi = 0; mi < 2; mi++)
        #pragma unroll
        for (int ni = 0; ni < 8; ni++)
            #pragma unroll
            for (int r = 0; r < 4; r++) acc[mi][ni][r] = 0.f;

    gemm_mainloop<true>(g, A, W, DD, acc);

    #pragma unroll
    for (int mi = 0; mi < 2; mi++)
        #pragma unroll
        for (int ni = 0; ni < 8; ni++) {
            int m = g.bm + g.wm*32 + mi*16 + g.lr;
            int n = g.bn + g.wn*64 + ni*8 + 2*g.lc;
            float2 bv = *(const float2*)(bias + n);
            float2 r0, r1;
            r0.x = fmaxf(acc[mi][ni][0] + bv.x, 0.f);
            r0.y = fmaxf(acc[mi][ni][1] + bv.y, 0.f);
            r1.x = fmaxf(acc[mi][ni][2] + bv.x, 0.f);
            r1.y = fmaxf(acc[mi][ni][3] + bv.y, 0.f);
            *(float2*)(C + (size_t)m*DD + n)     = r0;
            *(float2*)(C + (size_t)(m+8)*DD + n) = r1;
        }
}

// ---------------------------------------------------------------------------
// Causal flash attention, fp16 mma + ldmatrix fragments (round-6, unchanged).
// ---------------------------------------------------------------------------
#define FTILE (64*HST)

__global__ void __launch_bounds__(128, 3) flash_attn_h(
    const __half* __restrict__ Q, const __half* __restrict__ K,
    const __half* __restrict__ V, __half* __restrict__ Y)
{
    extern __shared__ __half smh[];
    __half* Ps = smh + 4*FTILE;

    const int tid  = threadIdx.x;
    const int lane = tid & 31;
    const int warp = tid >> 5;
    const int lr   = lane >> 2;
    const int lc   = lane & 3;
    const int qt   = blockIdx.x;
    const int bh   = blockIdx.y;
    const int r0   = warp*16 + lr;

    const __half* Qb = Q + (size_t)bh*SS*HDIM + (size_t)qt*64*HDIM;
    const __half* Kb = K + (size_t)bh*SS*HDIM;
    const __half* Vb = V + (size_t)bh*SS*HDIM;   // [d][key]

    uint32_t smem_base = (uint32_t)__cvta_generic_to_shared(smh);
    const uint32_t psbase = smem_base + (uint32_t)(4*FTILE*2);

    const int aRow = warp*16 + (lane & 15);
    const int aCol = (lane >> 4) << 3;
    const int bRow = (lane & 7) + ((lane & 16) >> 1);
    const int bCol = (lane & 8);

    const __half2 scale = __floats2half2_rn(0.125f, 0.125f);
    #pragma unroll
    for (int i = 0; i < 4; i++) {
        int idx = tid + i*128;
        int row = idx >> 3;
        int c8  = (idx & 7) << 3;
        uint4 raw = *(const uint4*)(Qb + row*HDIM + c8);
        __half2* h = (__half2*)&raw;
        h[0] = __hmul2(h[0], scale); h[1] = __hmul2(h[1], scale);
        h[2] = __hmul2(h[2], scale); h[3] = __hmul2(h[3], scale);
        *(uint4*)&Ps[row*HST + c8] = raw;
    }
    __syncthreads();

    uint32_t qf[4][4];
    #pragma unroll
    for (int ks = 0; ks < 4; ks++)
        ldmx4(qf[ks][0], qf[ks][1], qf[ks][2], qf[ks][3],
              psbase + (uint32_t)((aRow*HST + ks*16 + aCol) * 2));

    auto load_kv = [&](int kt, int buf) {
        const __half* Kt = Kb + (size_t)kt*64*HDIM;
        const __half* Vt = Vb + (size_t)kt*64;
        #pragma unroll
        for (int i = 0; i < 4; i++) {
            int idx = tid + i*128;
            int row = idx >> 3;
            int c8  = (idx & 7) << 3;
            uint32_t dK = smem_base + (uint32_t)((buf*FTILE + row*HST + c8)*2);
            asm volatile("cp.async.cg.shared.global [%0], [%1], 16;"
                         :: "r"(dK), "l"(Kt + row*HDIM + c8));
            uint32_t dV = smem_base + (uint32_t)(((2 + buf)*FTILE + row*HST + c8)*2);
            asm volatile("cp.async.cg.shared.global [%0], [%1], 16;"
                         :: "r"(dV), "l"(Vt + (size_t)row*SS + c8));
        }
        asm volatile("cp.async.commit_group;");
    };

    load_kv(0, 0);

    float m0 = -1e30f, m1 = -1e30f, l0 = 0.f, l1 = 0.f;
    float o[8][4];
    #pragma unroll
    for (int ni = 0; ni < 8; ni++)
        #pragma unroll
        for (int r = 0; r < 4; r++) o[ni][r] = 0.f;

    for (int kt = 0; kt <= qt; kt++) {
        const int buf = kt & 1;
        asm volatile("cp.async.wait_group 0;");
        __syncthreads();
        if (kt < qt) load_kv(kt + 1, buf ^ 1);

        const uint32_t kbuf = smem_base + (uint32_t)((buf*FTILE)*2);
        const uint32_t vbuf = smem_base + (uint32_t)(((2 + buf)*FTILE)*2);

        float s[8][4];
        #pragma unroll
        for (int ni = 0; ni < 8; ni++)
            #pragma unroll
            for (int r = 0; r < 4; r++) s[ni][r] = 0.f;

        #pragma unroll
        for (int ks = 0; ks < 4; ks++) {
            int kh = ks*16;
            uint32_t b[8][2];
            #pragma unroll
            for (int np = 0; np < 4; np++)
                ldmx4(b[2*np][0], b[2*np][1], b[2*np+1][0], b[2*np+1][1],
                      kbuf + (uint32_t)(((bRow + np*16)*HST + kh + bCol) * 2));
            #pragma unroll
            for (int ni = 0; ni < 8; ni++)
                MMA_F16(s[ni], qf[ks][0], qf[ks][1], qf[ks][2], qf[ks][3],
                        b[ni][0], b[ni][1]);
        }

        if (kt == qt) {
            #pragma unroll
            for (int ni = 0; ni < 8; ni++) {
                int c = ni*8 + 2*lc;
                if (c     > r0    ) s[ni][0] = -1e9f;
                if (c + 1 > r0    ) s[ni][1] = -1e9f;
                if (c     > r0 + 8) s[ni][2] = -1e9f;
                if (c + 1 > r0 + 8) s[ni][3] = -1e9f;
            }
        }

        float mx0 = -1e30f, mx1 = -1e30f;
        #pragma unroll
        for (int ni = 0; ni < 8; ni++) {
            mx0 = fmaxf(mx0, fmaxf(s[ni][0], s[ni][1]));
            mx1 = fmaxf(mx1, fmaxf(s[ni][2], s[ni][3]));
        }
        mx0 = fmaxf(mx0, __shfl_xor_sync(0xffffffffu, mx0, 1));
        mx0 = fmaxf(mx0, __shfl_xor_sync(0xffffffffu, mx0, 2));
        mx1 = fmaxf(mx1, __shfl_xor_sync(0xffffffffu, mx1, 1));
        mx1 = fmaxf(mx1, __shfl_xor_sync(0xffffffffu, mx1, 2));

        float mn0 = fmaxf(m0, mx0), mn1 = fmaxf(m1, mx1);
        float c0 = __expf(m0 - mn0), c1 = __expf(m1 - mn1);
        float rs0 = 0.f, rs1 = 0.f;
        #pragma unroll
        for (int ni = 0; ni < 8; ni++) {
            s[ni][0] = __expf(s[ni][0] - mn0);
            s[ni][1] = __expf(s[ni][1] - mn0);
            s[ni][2] = __expf(s[ni][2] - mn1);
            s[ni][3] = __expf(s[ni][3] - mn1);
            rs0 += s[ni][0] + s[ni][1];
            rs1 += s[ni][2] + s[ni][3];
        }
        rs0 += __shfl_xor_sync(0xffffffffu, rs0, 1);
        rs0 += __shfl_xor_sync(0xffffffffu, rs0, 2);
        rs1 += __shfl_xor_sync(0xffffffffu, rs1, 1);
        rs1 += __shfl_xor_sync(0xffffffffu, rs1, 2);
        l0 = l0*c0 + rs0;  m0 = mn0;
        l1 = l1*c1 + rs1;  m1 = mn1;

        #pragma unroll
        for (int ni = 0; ni < 8; ni++) {
            o[ni][0] *= c0;  o[ni][1] *= c0;
            o[ni][2] *= c1;  o[ni][3] *= c1;
            *(__half2*)&Ps[ r0     *HST + ni*8 + 2*lc] = __floats2half2_rn(s[ni][0], s[ni][1]);
            *(__half2*)&Ps[(r0 + 8)*HST + ni*8 + 2*lc] = __floats2half2_rn(s[ni][2], s[ni][3]);
        }
        __syncwarp();

        #pragma unroll
        for (int ks = 0; ks < 4; ks++) {
            int kh = ks*16;
            uint32_t a0, a1, a2, a3;
            ldmx4(a0, a1, a2, a3, psbase + (uint32_t)((aRow*HST + kh + aCol) * 2));
            uint32_t b[8][2];
            #pragma unroll
            for (int np = 0; np < 4; np++)
                ldmx4(b[2*np][0], b[2*np][1], b[2*np+1][0], b[2*np+1][1],
                      vbuf + (uint32_t)(((bRow + np*16)*HST + kh + bCol) * 2));
            #pragma unroll
            for (int ni = 0; ni < 8; ni++)
                MMA_F16(o[ni], a0, a1, a2, a3, b[ni][0], b[ni][1]);
        }
    }

    float inv0 = 1.f / l0, inv1 = 1.f / l1;
    __half* Yb = Y + (size_t)bh*SS*HDIM + (size_t)qt*64*HDIM;
    #pragma unroll
    for (int ni = 0; ni < 8; ni++) {
        int c = ni*8 + 2*lc;
        *(__half2*)(Yb + (size_t) r0     *HDIM + c) = __floats2half2_rn(o[ni][0]*inv0, o[ni][1]*inv0);
        *(__half2*)(Yb + (size_t)(r0 + 8)*HDIM + c) = __floats2half2_rn(o[ni][2]*inv1, o[ni][3]*inv1);
    }
}

// ---------------------------------------------------------------------------
extern "C" void kernel_launch(void* const* d_in, const int* in_sizes, int n_in,
                              void* d_out, int out_size) {
    const float* q  = (const float*)d_in[0];
    const float* k  = (const float*)d_in[1];
    const float* v  = (const float*)d_in[2];
    // d_in[3] = mask (int32 tril) — causal structure implemented directly
    const float* bq = (const float*)d_in[5];
    const float* bk = (const float*)d_in[7];
    const float* bv = (const float*)d_in[9];
    const float* bo = (const float*)d_in[11];
    float* out = (float*)d_out;

    __half *q16, *k16, *v16, *wq16, *wk16, *wv16, *wo16, *qh16, *kh16, *vht16, *y16;
    cudaGetSymbolAddress((void**)&q16,  g_q16);
    cudaGetSymbolAddress((void**)&k16,  g_k16);
    cudaGetSymbolAddress((void**)&v16,  g_v16);
    cudaGetSymbolAddress((void**)&wq16, g_wq16);
    cudaGetSymbolAddress((void**)&wk16, g_wk16);
    cudaGetSymbolAddress((void**)&wv16, g_wv16);
    cudaGetSymbolAddress((void**)&wo16, g_wo16);
    cudaGetSymbolAddress((void**)&qh16, g_qh16);
    cudaGetSymbolAddress((void**)&kh16, g_kh16);
    cudaGetSymbolAddress((void**)&vht16, g_vht16);
    cudaGetSymbolAddress((void**)&y16,  g_y16);

    CvtArgs ca;
    ca.src[0] = q;                      ca.dst[0] = q16;  ca.n[0] = BB*SS*DD;
    ca.src[1] = k;                      ca.dst[1] = k16;  ca.n[1] = BB*SS*DD;
    ca.src[2] = v;                      ca.dst[2] = v16;  ca.n[2] = BB*SS*DD;
    ca.src[3] = (const float*)d_in[4];  ca.dst[3] = wq16; ca.n[3] = DD*DD;
    ca.src[4] = (const float*)d_in[6];  ca.dst[4] = wk16; ca.n[4] = DD*DD;
    ca.src[5] = (const float*)d_in[8];  ca.dst[5] = wv16; ca.n[5] = DD*DD;
    ca.src[6] = (const float*)d_in[10]; ca.dst[6] = wo16; ca.n[6] = DD*DD;
    convert_all<<<dim3(2048, 7), 256>>>(ca);

    cudaFuncSetAttribute(gemm_qkv, cudaFuncAttributeMaxDynamicSharedMemorySize, GEMM_SMEM);
    cudaFuncSetAttribute(gemm_out, cudaFuncAttributeMaxDynamicSharedMemorySize, GEMM_SMEM);

    QKVArgs qa;
    qa.A[0] = q16;  qa.W[0] = wq16; qa.b[0] = bq; qa.C[0] = qh16;
    qa.A[1] = k16;  qa.W[1] = wk16; qa.b[1] = bk; qa.C[1] = kh16;
    qa.A[2] = v16;  qa.W[2] = wv16; qa.b[2] = bv; qa.C[2] = vht16;

    dim3 qkvgrid(DD/128, (BB*SS)/128, 3);   // (8, 32, 3) = 768 CTAs
    gemm_qkv<<<qkvgrid, 256, GEMM_SMEM>>>(qa);

    const int flash_smem = 5 * FTILE * (int)sizeof(__half);  // 46080 B
    cudaFuncSetAttribute(flash_attn_h, cudaFuncAttributeMaxDynamicSharedMemorySize, flash_smem);
    flash_attn_h<<<dim3(SS/64, NBH), 128, flash_smem>>>(qh16, kh16, vht16, y16);

    dim3 ogrid(DD/128, (BB*SS)/128);        // (8, 32)
    gemm_out<<<ogrid, 256, GEMM_SMEM>>>(y16, wo16, bo, out);
}